// round 14
// baseline (speedup 1.0000x reference)
#include <cuda_runtime.h>
#include <cuda_fp16.h>
#include <cstdint>

#define NROWS 8192
#define DD    512

// GEMM tile: BM=128, BN=128, BK=32, 256 threads, warp grid 2(m) x 4(n), warp tile 64x32
#define BM 128
#define BN 128
#define BK 32
#define ASTRIDE 80                 // bytes per A smem row (32 halves + pad); LDSM conflict-free
#define BSTRIDE 544                // bytes per B smem pair-row; conflict-free
#define A_TILE (BM*ASTRIDE)        // 10240
#define B_TILE ((BK/2)*BSTRIDE)    // 8704
#define STAGE  (A_TILE + B_TILE)   // 18944
#define NSTAGE 4
#define SMEM_TOTAL (NSTAGE*STAGE)  // 75776
#define HG_OFF   SMEM_TOTAL
#define SB_OFF   (HG_OFF + DD*4)
#define FINAL_SMEM (SB_OFF + 128*4)

#define HP_SZ ((size_t)NROWS*DD)

// ---------------- device scratch ----------------
__device__ __half  g_xfH[NROWS*DD];      // xf fp16 row-major
__device__ __half2 g_xfP[(NROWS/2)*DD];  // xf k-pair-packed [k/2][n]
__device__ __half  g_hp[4*NROWS*DD];     // partials: [mat(2)][kh(2)] half-K results
__device__ __half  g_yx[NROWS*DD];       // xf @ W^T, fp16
__device__ __half2 g_WP  [(DD/2)*DD];
__device__ __half2 g_WudP[(DD/2)*DD];
__device__ __half2 g_WlrP[(DD/2)*DD];
__device__ __half2 g_WgP [(DD/2)*DD];
__device__ float   g_pooled[DD];
__device__ float   g_nsum;

// ---------------- helpers ----------------
__device__ __forceinline__ uint32_t smem_u32(const void* p){
    return (uint32_t)__cvta_generic_to_shared(p);
}
__device__ __forceinline__ void cpasync16(uint32_t s, const void* g){
    asm volatile("cp.async.cg.shared.global [%0], [%1], 16;\n" :: "r"(s), "l"(g));
}
__device__ __forceinline__ void hmma(float* c, const uint32_t a[4], const uint32_t b[2]){
    asm volatile(
      "mma.sync.aligned.m16n8k16.row.col.f32.f16.f16.f32 "
      "{%0,%1,%2,%3},{%4,%5,%6,%7},{%8,%9},{%0,%1,%2,%3};\n"
      : "+f"(c[0]),"+f"(c[1]),"+f"(c[2]),"+f"(c[3])
      : "r"(a[0]),"r"(a[1]),"r"(a[2]),"r"(a[3]),"r"(b[0]),"r"(b[1]));
}
__device__ __forceinline__ void ldsm4(uint32_t* r, uint32_t addr){
    asm volatile("ldmatrix.sync.aligned.m8n8.x4.shared.b16 {%0,%1,%2,%3}, [%4];"
        : "=r"(r[0]),"=r"(r[1]),"=r"(r[2]),"=r"(r[3]) : "r"(addr));
}
__device__ __forceinline__ uint32_t lds32(uint32_t addr){
    uint32_t v; asm volatile("ld.shared.b32 %0, [%1];" : "=r"(v) : "r"(addr)); return v;
}
__device__ __forceinline__ void sts_u2(uint32_t addr, uint32_t x, uint32_t y){
    asm volatile("st.shared.v2.b32 [%0], {%1,%2};" :: "r"(addr), "r"(x), "r"(y));
}
__device__ __forceinline__ void sts_u4(uint32_t addr, uint4 v){
    asm volatile("st.shared.v4.b32 [%0], {%1,%2,%3,%4};"
        :: "r"(addr), "r"(v.x), "r"(v.y), "r"(v.z), "r"(v.w));
}
__device__ __forceinline__ uint32_t hadd2u(uint32_t a, uint32_t b){
    __half2 r = __hadd2(*(__half2*)&a, *(__half2*)&b); return *(uint32_t*)&r;
}
// conflict-free A-chunk mapping for 16B STS at ASTRIDE=80
__device__ __forceinline__ void amap(int idx, int& m, int& c){
    int q = idx>>2; c = idx&3;
    m = (q & 0x78) | ((q & 1) << 2) | ((q >> 1) & 3);
}

#define ZERO_ACC(acc) do{ _Pragma("unroll") for(int i_=0;i_<4;i_++) \
    _Pragma("unroll") for(int j_=0;j_<4;j_++) \
    _Pragma("unroll") for(int q_=0;q_<4;q_++) acc[i_][j_][q_]=0.f; }while(0)

// One BK=32 tile of MMAs. A via ldmatrix.x4, B via LDS.32.
__device__ __forceinline__ void compute_tile(uint32_t As, uint32_t Bs,
                                             float (&acc)[4][4][4],
                                             int wm,int wn,int gq,int tq,int lane){
    const uint32_t arow = lane & 15;
    const uint32_t acol = (lane >> 4) * 16;
    const uint32_t abase = As + (wm + arow)*ASTRIDE + acol;
    const uint32_t bbase = Bs + tq*BSTRIDE + (wn + gq)*4;
    #pragma unroll
    for(int kk=0;kk<2;kk++){
        uint32_t a[4][4], b[4][2];
        #pragma unroll
        for(int mt=0;mt<4;mt++)
            ldsm4(a[mt], abase + mt*16*ASTRIDE + kk*32);
        #pragma unroll
        for(int nt=0;nt<4;nt++){
            uint32_t p = bbase + kk*8*BSTRIDE + nt*32;
            b[nt][0] = lds32(p);
            b[nt][1] = lds32(p + 4*BSTRIDE);
        }
        #pragma unroll
        for(int mt=0;mt<4;mt++)
            #pragma unroll
            for(int nt=0;nt<4;nt++)
                hmma(acc[mt][nt], a[mt], b[nt]);
    }
}

// ---- mainloop A: A fp32 global, converted in-flight ----
template<class FA, class FB>
__device__ __forceinline__ void mainloop_conv(int nk, float (&acc)[4][4][4],
                                              char* sm, FA getAf4, FB getB16){
    const int tid = threadIdx.x;
    const uint32_t smb = smem_u32(sm);
    const int lane=tid&31, warp=tid>>5;
    const int wm=(warp>>2)*64, wn=(warp&3)*32, gq=lane>>2, tq=lane&3;

    float4 av[4];
    #pragma unroll
    for(int r=0;r<4;r++) av[r] = __ldg(getAf4(0, tid + r*256));

    #pragma unroll
    for(int pg=0; pg<2; pg++){
        if(pg < nk){
            const uint32_t bb = smb + pg*STAGE + A_TILE;
            #pragma unroll
            for(int r=0;r<2;r++){
                int idx = tid + r*256; int p=idx>>5, c=idx&31;
                cpasync16(bb + p*BSTRIDE + c*16, getB16(pg, idx));
            }
        }
        asm volatile("cp.async.commit_group;" ::: "memory");
    }

    for(int kt=0; kt<nk; ++kt){
        const uint32_t ab = smb + (kt&3)*STAGE;
        #pragma unroll
        for(int r=0;r<4;r++){
            int idx = tid + r*256; int m=idx>>3, c=idx&7;
            __half2 h0 = __floats2half2_rn(av[r].x, av[r].y);
            __half2 h1 = __floats2half2_rn(av[r].z, av[r].w);
            sts_u2(ab + m*ASTRIDE + c*8, *(uint32_t*)&h0, *(uint32_t*)&h1);
        }
        if(kt+1 < nk){
            #pragma unroll
            for(int r=0;r<4;r++) av[r] = __ldg(getAf4(kt+1, tid + r*256));
        }
        if(kt+2 < nk){
            const uint32_t bb = smb + ((kt+2)&3)*STAGE + A_TILE;
            #pragma unroll
            for(int r=0;r<2;r++){
                int idx = tid + r*256; int p=idx>>5, c=idx&31;
                cpasync16(bb + p*BSTRIDE + c*16, getB16(kt+2, idx));
            }
        }
        asm volatile("cp.async.commit_group;" ::: "memory");
        asm volatile("cp.async.wait_group 2;" ::: "memory");
        __syncthreads();
        compute_tile(ab, ab + A_TILE, acc, wm, wn, gq, tq, lane);
    }
}

// ---- mainloop B: both operands via cp.async ----
template<class FA, class FB>
__device__ __forceinline__ void mainloop_cp(int nk, float (&acc)[4][4][4],
                                            char* sm, FA getA16, FB getB16){
    const int tid = threadIdx.x;
    const uint32_t smb = smem_u32(sm);
    const int lane=tid&31, warp=tid>>5;
    const int wm=(warp>>2)*64, wn=(warp&3)*32, gq=lane>>2, tq=lane&3;

    auto stage_loads = [&](int s){
        const uint32_t ab = smb + (s&3)*STAGE;
        const uint32_t bb = ab + A_TILE;
        #pragma unroll
        for(int r=0;r<2;r++){
            int idx = tid + r*256; int m=idx>>2, c=idx&3;
            cpasync16(ab + m*ASTRIDE + c*16, getA16(s, idx));
        }
        #pragma unroll
        for(int r=0;r<2;r++){
            int idx = tid + r*256; int p=idx>>5, c=idx&31;
            cpasync16(bb + p*BSTRIDE + c*16, getB16(s, idx));
        }
    };

    #pragma unroll
    for(int pg=0; pg<2; pg++){
        if(pg < nk) stage_loads(pg);
        asm volatile("cp.async.commit_group;" ::: "memory");
    }
    for(int kt=0; kt<nk; ++kt){
        if(kt+2 < nk) stage_loads(kt+2);
        asm volatile("cp.async.commit_group;" ::: "memory");
        asm volatile("cp.async.wait_group 2;" ::: "memory");
        __syncthreads();
        const uint32_t ab = smb + (kt&3)*STAGE;
        compute_tile(ab, ab + A_TILE, acc, wm, wn, gq, tq, lane);
    }
}

// ---- mainloop C: A = sum of two fp16 sources (LDG + HADD2 + STS), B via cp.async ----
template<class FA0, class FA1, class FB>
__device__ __forceinline__ void mainloop_sum(int nk, float (&acc)[4][4][4],
                                             char* sm, FA0 getA0, FA1 getA1, FB getB16){
    const int tid = threadIdx.x;
    const uint32_t smb = smem_u32(sm);
    const int lane=tid&31, warp=tid>>5;
    const int wm=(warp>>2)*64, wn=(warp&3)*32, gq=lane>>2, tq=lane&3;
    int am[2], ac[2];
    amap(tid,     am[0], ac[0]);
    amap(tid+256, am[1], ac[1]);

    auto cpB = [&](int s){
        const uint32_t bb = smb + (s&3)*STAGE + A_TILE;
        #pragma unroll
        for(int r=0;r<2;r++){
            int idx = tid + r*256; int p=idx>>5, c=idx&31;
            cpasync16(bb + p*BSTRIDE + c*16, getB16(s, idx));
        }
    };
    auto ldA = [&](int s, uint4 (*sv)[2]){
        #pragma unroll
        for(int r=0;r<2;r++){
            sv[r][0] = __ldg((const uint4*)getA0(s, am[r], ac[r]));
            sv[r][1] = __ldg((const uint4*)getA1(s, am[r], ac[r]));
        }
    };
    auto stA = [&](int s, uint4 (*sv)[2]){
        const uint32_t ab = smb + (s&3)*STAGE;
        #pragma unroll
        for(int r=0;r<2;r++){
            uint4 v;
            v.x = hadd2u(sv[r][0].x, sv[r][1].x);
            v.y = hadd2u(sv[r][0].y, sv[r][1].y);
            v.z = hadd2u(sv[r][0].z, sv[r][1].z);
            v.w = hadd2u(sv[r][0].w, sv[r][1].w);
            sts_u4(ab + am[r]*ASTRIDE + ac[r]*16, v);
        }
    };

    uint4 sv[2][2];
    ldA(0, sv);
    cpB(0); asm volatile("cp.async.commit_group;" ::: "memory");
    if(nk>1) cpB(1);
    asm volatile("cp.async.commit_group;" ::: "memory");

    for(int kt=0; kt<nk; ++kt){
        stA(kt, sv);
        if(kt+1 < nk) ldA(kt+1, sv);
        if(kt+2 < nk) cpB(kt+2);
        asm volatile("cp.async.commit_group;" ::: "memory");
        asm volatile("cp.async.wait_group 2;" ::: "memory");
        __syncthreads();
        const uint32_t ab = smb + (kt&3)*STAGE;
        compute_tile(ab, ab + A_TILE, acc, wm, wn, gq, tq, lane);
    }
}

// ---------------- prep ----------------
__global__ void prep_kernel(const float* __restrict__ xf, const float* __restrict__ mask,
                            const float* __restrict__ W,  const float* __restrict__ Wud,
                            const float* __restrict__ Wlr,const float* __restrict__ Wg){
    const int bx = blockIdx.x, tid = threadIdx.x;
    if(bx < 2048){
        int idx = bx*256 + tid;
        int p = idx >> 7, n4 = (idx & 127)*4;
        float4 v0 = *(const float4*)(xf + (size_t)(2*p)*DD + n4);
        float4 v1 = *(const float4*)(xf + (size_t)(2*p+1)*DD + n4);
        __half2 r0 = __floats2half2_rn(v0.x, v0.y), r1 = __floats2half2_rn(v0.z, v0.w);
        __half2 r2 = __floats2half2_rn(v1.x, v1.y), r3 = __floats2half2_rn(v1.z, v1.w);
        uint2 u0; u0.x=*(uint32_t*)&r0; u0.y=*(uint32_t*)&r1;
        uint2 u1; u1.x=*(uint32_t*)&r2; u1.y=*(uint32_t*)&r3;
        *(uint2*)(g_xfH + (size_t)(2*p)*DD + n4)   = u0;
        *(uint2*)(g_xfH + (size_t)(2*p+1)*DD + n4) = u1;
        __half2 p0 = __floats2half2_rn(v0.x, v1.x);
        __half2 p1 = __floats2half2_rn(v0.y, v1.y);
        __half2 p2 = __floats2half2_rn(v0.z, v1.z);
        __half2 p3 = __floats2half2_rn(v0.w, v1.w);
        uint4 up; up.x=*(uint32_t*)&p0; up.y=*(uint32_t*)&p1; up.z=*(uint32_t*)&p2; up.w=*(uint32_t*)&p3;
        *(uint4*)(g_xfP + (size_t)p*DD + n4) = up;
    } else if(bx < 4096){
        int i = bx - 2048;
        const float* src; __half2* dst;
        switch(i >> 9){
            case 0: src=W;   dst=g_WP;   break;
            case 1: src=Wud; dst=g_WudP; break;
            case 2: src=Wlr; dst=g_WlrP; break;
            default:src=Wg;  dst=g_WgP;  break;
        }
        int idx = (i & 511)*256 + tid;
        int p = idx >> 9, n = idx & 511;
        float2 v = *(const float2*)(src + (size_t)n*DD + 2*p);
        dst[(size_t)p*DD + n] = __floats2half2_rn(v.x, v.y);
    } else {
        __shared__ float red[256];
        float s=0.f;
        for(int i=tid;i<NROWS;i+=256) s += mask[i];
        red[tid]=s; __syncthreads();
        for(int st=128;st>0;st>>=1){
            if(tid<st) red[tid]+=red[tid+st];
            __syncthreads();
        }
        if(tid==0) g_nsum = red[0];
        g_pooled[tid]     = 0.f;
        g_pooled[tid+256] = 0.f;
    }
}

// ---------------- mega: half-K big aggregations + pool + y_x ----------------
// Big CTA map: col fastest (R9 win) so the 4 CTAs sharing an A row-slab co-reside.
__global__ void __launch_bounds__(256,2) mega_kernel(
        const float* __restrict__ a_ud, const float* __restrict__ a_lr,
        const float* __restrict__ b_g,  const float* __restrict__ mask){
    extern __shared__ char sm[];
    const int bx = blockIdx.x;
    const int lane=threadIdx.x&31, warp=threadIdx.x>>5;
    const int wm=(warp>>2)*64, wn=(warp&3)*32, gq=lane>>2, tq=lane&3;
    float acc[4][4][4]; ZERO_ACC(acc);

    if(bx < 1024){
        // mat(2) x half(2) x row(64) x col(4), col fastest
        const int mat = bx>>9, half = (bx>>8)&1, row = (bx>>2)&63, col = bx&3;
        const float* A = mat ? a_lr : a_ud;
        __half* C = g_hp + (size_t)(mat*2 + half)*HP_SZ;
        const size_t rowBase = (size_t)row * BM;
        const int colBase = col * BN;
        const int kOff = half * 4096;
        auto getAf4=[&](int s,int idx){
            int m=idx>>3, c=idx&7;
            return (const float4*)(A + (rowBase+m)*NROWS + kOff + s*BK + c*4);
        };
        auto getB16=[&](int s,int idx){
            int p=idx>>5, c=idx&31;
            return (const void*)(g_xfP + (size_t)(kOff/2 + s*16 + p)*DD + colBase + c*4);
        };
        mainloop_conv(4096/BK, acc, sm, getAf4, getB16);
        #pragma unroll
        for(int mt=0;mt<4;mt++){
            size_t r0 = rowBase + wm + mt*16 + gq;
            #pragma unroll
            for(int nt=0;nt<4;nt++){
                int c0 = colBase + wn + nt*8 + 2*tq;
                *(__half2*)(C + r0*DD + c0)     = __floats2half2_rn(acc[mt][nt][0], acc[mt][nt][1]);
                *(__half2*)(C + (r0+8)*DD + c0) = __floats2half2_rn(acc[mt][nt][2], acc[mt][nt][3]);
            }
        }
    } else if(bx < 1280){
        const int i = bx - 1024;
        const size_t rowBase = (size_t)(i & 63) * BM;
        const int colBase = (i >> 6) * BN;
        auto getA16=[&](int s,int idx){
            int m=idx>>2, c=idx&3;
            return (const void*)(g_xfH + (rowBase+m)*DD + s*BK + c*8);
        };
        auto getB16=[&](int s,int idx){
            int p=idx>>5, c=idx&31;
            return (const void*)(g_WgP + (size_t)(s*16+p)*DD + colBase + c*4);
        };
        mainloop_cp(DD/BK, acc, sm, getA16, getB16);
        float cs[4][2];
        #pragma unroll
        for(int nt=0;nt<4;nt++){ cs[nt][0]=0.f; cs[nt][1]=0.f; }
        #pragma unroll
        for(int mt=0;mt<4;mt++){
            size_t r0 = rowBase + wm + mt*16 + gq;
            float m0 = mask[r0], m8 = mask[r0+8];
            #pragma unroll
            for(int nt=0;nt<4;nt++){
                int c0 = colBase + wn + nt*8 + 2*tq;
                float bg0 = b_g[c0], bg1 = b_g[c0+1];
                cs[nt][0] += fmaxf(acc[mt][nt][0]+bg0,0.f)*m0 + fmaxf(acc[mt][nt][2]+bg0,0.f)*m8;
                cs[nt][1] += fmaxf(acc[mt][nt][1]+bg1,0.f)*m0 + fmaxf(acc[mt][nt][3]+bg1,0.f)*m8;
            }
        }
        #pragma unroll
        for(int nt=0;nt<4;nt++){
            #pragma unroll
            for(int j=0;j<2;j++){
                float v = cs[nt][j];
                v += __shfl_xor_sync(0xffffffffu, v, 4);
                v += __shfl_xor_sync(0xffffffffu, v, 8);
                v += __shfl_xor_sync(0xffffffffu, v, 16);
                if(lane < 4)
                    atomicAdd(&g_pooled[colBase + wn + nt*8 + 2*tq + j], v);
            }
        }
    } else {
        const int i = bx - 1280;
        const size_t rowBase = (size_t)(i & 63) * BM;
        const int colBase = (i >> 6) * BN;
        auto getA16=[&](int s,int idx){
            int m=idx>>2, c=idx&3;
            return (const void*)(g_xfH + (rowBase+m)*DD + s*BK + c*8);
        };
        auto getB16=[&](int s,int idx){
            int p=idx>>5, c=idx&31;
            return (const void*)(g_WP + (size_t)(s*16+p)*DD + colBase + c*4);
        };
        mainloop_cp(DD/BK, acc, sm, getA16, getB16);
        #pragma unroll
        for(int mt=0;mt<4;mt++){
            size_t r0 = rowBase + wm + mt*16 + gq;
            #pragma unroll
            for(int nt=0;nt<4;nt++){
                int c0 = colBase + wn + nt*8 + 2*tq;
                *(__half2*)(g_yx + r0*DD + c0)     = __floats2half2_rn(acc[mt][nt][0], acc[mt][nt][1]);
                *(__half2*)(g_yx + (r0+8)*DD + c0) = __floats2half2_rn(acc[mt][nt][2], acc[mt][nt][3]);
            }
        }
    }
}

// ---------------- final: h = relu( y_x + h_ud@Wud^T + h_lr@Wlr^T + bias ) ----------------
__global__ void __launch_bounds__(256,2) final_kernel(
        const float* __restrict__ W_go,
        const float* __restrict__ b,   const float* __restrict__ b_ud,
        const float* __restrict__ b_lr,const float* __restrict__ b_go,
        float* __restrict__ out){
    extern __shared__ char sm[];
    float* hg    = (float*)(sm + HG_OFF);
    float* sbias = (float*)(sm + SB_OFF);
    const int tid = threadIdx.x;
    const size_t rowBase = (size_t)(blockIdx.x & 63) * BM;
    const int colBase = (blockIdx.x >> 6) * BN;

    {
        float inv = 1.0f / g_nsum;
        hg[tid]     = g_pooled[tid]*inv;
        hg[tid+256] = g_pooled[tid+256]*inv;
    }
    __syncthreads();
    if(blockIdx.x == 0){
        out[HP_SZ + tid]       = hg[tid];
        out[HP_SZ + tid + 256] = hg[tid+256];
    }
    {
        int j = colBase + (tid>>1);
        int k0 = (tid&1)*256;
        const float4* wr = (const float4*)(W_go + (size_t)j*DD + k0);
        float s = 0.f;
        #pragma unroll 8
        for(int q=0;q<64;q++){
            float4 wv = wr[q];
            s += hg[k0+4*q]*wv.x + hg[k0+4*q+1]*wv.y + hg[k0+4*q+2]*wv.z + hg[k0+4*q+3]*wv.w;
        }
        s += __shfl_xor_sync(0xffffffffu, s, 1);
        if((tid&1)==0) sbias[tid>>1] = s + b[j] + b_ud[j] + b_lr[j] + b_go[j];
    }
    __syncthreads();

    float acc[4][4][4]; ZERO_ACC(acc);
    // K=1024: seg 0 = h_ud (partials 0,1), seg 1 = h_lr (partials 2,3)
    auto getA0=[&](int s,int m,int c){
        int seg = s>>4;
        const __half* A = g_hp + (size_t)(seg*2)*HP_SZ;
        return (const void*)(A + (rowBase+m)*DD + (s&15)*BK + c*8);
    };
    auto getA1=[&](int s,int m,int c){
        int seg = s>>4;
        const __half* A = g_hp + (size_t)(seg*2+1)*HP_SZ;
        return (const void*)(A + (rowBase+m)*DD + (s&15)*BK + c*8);
    };
    auto getB16=[&](int s,int idx){
        int p=idx>>5, c=idx&31; int seg=s>>4;
        const __half2* B = seg ? g_WlrP : g_WudP;
        return (const void*)(B + (size_t)((s&15)*16+p)*DD + colBase + c*4);
    };
    mainloop_sum(2*DD/BK, acc, sm, getA0, getA1, getB16);

    const int lane=tid&31, warp=tid>>5;
    const int wm=(warp>>2)*64, wn=(warp&3)*32, gq=lane>>2, tq=lane&3;
    #pragma unroll
    for(int mt=0;mt<4;mt++){
        size_t r0 = rowBase + wm + mt*16 + gq;
        #pragma unroll
        for(int nt=0;nt<4;nt++){
            int c0 = colBase + wn + nt*8 + 2*tq;
            float bb0 = sbias[c0-colBase], bb1 = sbias[c0-colBase+1];
            float2 y0 = __half22float2(*(const __half2*)(g_yx + r0*DD + c0));
            float2 y2 = __half22float2(*(const __half2*)(g_yx + (r0+8)*DD + c0));
            float2 v0 = make_float2(fmaxf(acc[mt][nt][0]+y0.x+bb0,0.f),
                                    fmaxf(acc[mt][nt][1]+y0.y+bb1,0.f));
            float2 v2 = make_float2(fmaxf(acc[mt][nt][2]+y2.x+bb0,0.f),
                                    fmaxf(acc[mt][nt][3]+y2.y+bb1,0.f));
            *(float2*)(out + r0*DD + c0)     = v0;
            *(float2*)(out + (r0+8)*DD + c0) = v2;
        }
    }
}

// ---------------- launch ----------------
extern "C" void kernel_launch(void* const* d_in, const int* in_sizes, int n_in,
                              void* d_out, int out_size){
    const float* x    = (const float*)d_in[0];
    const float* mask = (const float*)d_in[1];
    const float* a_ud = (const float*)d_in[2];
    const float* a_lr = (const float*)d_in[3];
    const float* W    = (const float*)d_in[4];
    const float* b    = (const float*)d_in[5];
    const float* W_ud = (const float*)d_in[6];
    const float* b_ud = (const float*)d_in[7];
    const float* W_lr = (const float*)d_in[8];
    const float* b_lr = (const float*)d_in[9];
    const float* W_g  = (const float*)d_in[10];
    const float* b_g  = (const float*)d_in[11];
    const float* W_go = (const float*)d_in[12];
    const float* b_go = (const float*)d_in[13];
    float* out = (float*)d_out;

    cudaFuncSetAttribute(mega_kernel,  cudaFuncAttributeMaxDynamicSharedMemorySize, SMEM_TOTAL);
    cudaFuncSetAttribute(final_kernel, cudaFuncAttributeMaxDynamicSharedMemorySize, FINAL_SMEM);

    prep_kernel<<<4097, 256>>>(x, mask, W, W_ud, W_lr, W_g);
    mega_kernel<<<1536, 256, SMEM_TOTAL>>>(a_ud, a_lr, b_g, mask);
    final_kernel<<<256, 256, FINAL_SMEM>>>(W_go, b, b_ud, b_lr, b_go, out);
}

// round 15
// speedup vs baseline: 1.5271x; 1.5271x over previous
#include <cuda_runtime.h>
#include <cuda_fp16.h>
#include <cstdint>

#define NROWS 8192
#define DD    512

// GEMM tile: BM=128, BN=128, BK=32, 256 threads, warp grid 2(m) x 4(n), warp tile 64x32
#define BM 128
#define BN 128
#define BK 32
#define ASTRIDE 80                 // bytes per A smem row (32 halves + pad); LDSM conflict-free
#define BSTRIDE 544                // bytes per B smem pair-row; conflict-free
#define A_TILE (BM*ASTRIDE)        // 10240
#define B_TILE ((BK/2)*BSTRIDE)    // 8704
#define STAGE  (A_TILE + B_TILE)   // 18944
#define NSTAGE 4
#define SMEM_TOTAL (NSTAGE*STAGE)  // 75776
#define HG_OFF   SMEM_TOTAL
#define SB_OFF   (HG_OFF + DD*4)
#define FINAL_SMEM (SB_OFF + 128*4)

#define HP_SZ ((size_t)NROWS*DD)

// ---------------- device scratch ----------------
__device__ __half  g_xfH[NROWS*DD];      // xf fp16 row-major
__device__ __half2 g_xfP[(NROWS/2)*DD];  // xf k-pair-packed [k/2][n]
__device__ __half  g_hp[4*NROWS*DD];     // partials: [mat(2)][kh(2)] half-K results
__device__ __half  g_yx[NROWS*DD];       // xf @ W^T, fp16
__device__ __half2 g_WP  [(DD/2)*DD];
__device__ __half2 g_WudP[(DD/2)*DD];
__device__ __half2 g_WlrP[(DD/2)*DD];
__device__ __half2 g_WgP [(DD/2)*DD];
__device__ float   g_pooled[DD];
__device__ float   g_nsum;

// ---------------- helpers ----------------
__device__ __forceinline__ uint32_t smem_u32(const void* p){
    return (uint32_t)__cvta_generic_to_shared(p);
}
__device__ __forceinline__ void cpasync16(uint32_t s, const void* g){
    asm volatile("cp.async.cg.shared.global [%0], [%1], 16;\n" :: "r"(s), "l"(g));
}
__device__ __forceinline__ void hmma(float* c, const uint32_t a[4], const uint32_t b[2]){
    asm volatile(
      "mma.sync.aligned.m16n8k16.row.col.f32.f16.f16.f32 "
      "{%0,%1,%2,%3},{%4,%5,%6,%7},{%8,%9},{%0,%1,%2,%3};\n"
      : "+f"(c[0]),"+f"(c[1]),"+f"(c[2]),"+f"(c[3])
      : "r"(a[0]),"r"(a[1]),"r"(a[2]),"r"(a[3]),"r"(b[0]),"r"(b[1]));
}
__device__ __forceinline__ void ldsm4(uint32_t* r, uint32_t addr){
    asm volatile("ldmatrix.sync.aligned.m8n8.x4.shared.b16 {%0,%1,%2,%3}, [%4];"
        : "=r"(r[0]),"=r"(r[1]),"=r"(r[2]),"=r"(r[3]) : "r"(addr));
}
__device__ __forceinline__ uint32_t lds32(uint32_t addr){
    uint32_t v; asm volatile("ld.shared.b32 %0, [%1];" : "=r"(v) : "r"(addr)); return v;
}
__device__ __forceinline__ void sts_u2(uint32_t addr, uint32_t x, uint32_t y){
    asm volatile("st.shared.v2.b32 [%0], {%1,%2};" :: "r"(addr), "r"(x), "r"(y));
}
__device__ __forceinline__ void sts_u4(uint32_t addr, uint4 v){
    asm volatile("st.shared.v4.b32 [%0], {%1,%2,%3,%4};"
        :: "r"(addr), "r"(v.x), "r"(v.y), "r"(v.z), "r"(v.w));
}
__device__ __forceinline__ uint32_t hadd2u(uint32_t a, uint32_t b){
    __half2 r = __hadd2(*(__half2*)&a, *(__half2*)&b); return *(uint32_t*)&r;
}
// conflict-free A-chunk mapping for 16B STS at ASTRIDE=80
__device__ __forceinline__ void amap(int idx, int& m, int& c){
    int q = idx>>2; c = idx&3;
    m = (q & 0x78) | ((q & 1) << 2) | ((q >> 1) & 3);
}

#define ZERO_ACC(acc) do{ _Pragma("unroll") for(int i_=0;i_<4;i_++) \
    _Pragma("unroll") for(int j_=0;j_<4;j_++) \
    _Pragma("unroll") for(int q_=0;q_<4;q_++) acc[i_][j_][q_]=0.f; }while(0)

// One BK=32 tile of MMAs. A via ldmatrix.x4, B via LDS.32.
__device__ __forceinline__ void compute_tile(uint32_t As, uint32_t Bs,
                                             float (&acc)[4][4][4],
                                             int wm,int wn,int gq,int tq,int lane){
    const uint32_t arow = lane & 15;
    const uint32_t acol = (lane >> 4) * 16;
    const uint32_t abase = As + (wm + arow)*ASTRIDE + acol;
    const uint32_t bbase = Bs + tq*BSTRIDE + (wn + gq)*4;
    #pragma unroll
    for(int kk=0;kk<2;kk++){
        uint32_t a[4][4], b[4][2];
        #pragma unroll
        for(int mt=0;mt<4;mt++)
            ldsm4(a[mt], abase + mt*16*ASTRIDE + kk*32);
        #pragma unroll
        for(int nt=0;nt<4;nt++){
            uint32_t p = bbase + kk*8*BSTRIDE + nt*32;
            b[nt][0] = lds32(p);
            b[nt][1] = lds32(p + 4*BSTRIDE);
        }
        #pragma unroll
        for(int mt=0;mt<4;mt++)
            #pragma unroll
            for(int nt=0;nt<4;nt++)
                hmma(acc[mt][nt], a[mt], b[nt]);
    }
}

// ---- mainloop A: A fp32 global, converted in-flight ----
template<class FA, class FB>
__device__ __forceinline__ void mainloop_conv(int nk, float (&acc)[4][4][4],
                                              char* sm, FA getAf4, FB getB16){
    const int tid = threadIdx.x;
    const uint32_t smb = smem_u32(sm);
    const int lane=tid&31, warp=tid>>5;
    const int wm=(warp>>2)*64, wn=(warp&3)*32, gq=lane>>2, tq=lane&3;

    float4 av[4];
    #pragma unroll
    for(int r=0;r<4;r++) av[r] = __ldg(getAf4(0, tid + r*256));

    #pragma unroll
    for(int pg=0; pg<2; pg++){
        if(pg < nk){
            const uint32_t bb = smb + pg*STAGE + A_TILE;
            #pragma unroll
            for(int r=0;r<2;r++){
                int idx = tid + r*256; int p=idx>>5, c=idx&31;
                cpasync16(bb + p*BSTRIDE + c*16, getB16(pg, idx));
            }
        }
        asm volatile("cp.async.commit_group;" ::: "memory");
    }

    for(int kt=0; kt<nk; ++kt){
        const uint32_t ab = smb + (kt&3)*STAGE;
        #pragma unroll
        for(int r=0;r<4;r++){
            int idx = tid + r*256; int m=idx>>3, c=idx&7;
            __half2 h0 = __floats2half2_rn(av[r].x, av[r].y);
            __half2 h1 = __floats2half2_rn(av[r].z, av[r].w);
            sts_u2(ab + m*ASTRIDE + c*8, *(uint32_t*)&h0, *(uint32_t*)&h1);
        }
        if(kt+1 < nk){
            #pragma unroll
            for(int r=0;r<4;r++) av[r] = __ldg(getAf4(kt+1, tid + r*256));
        }
        if(kt+2 < nk){
            const uint32_t bb = smb + ((kt+2)&3)*STAGE + A_TILE;
            #pragma unroll
            for(int r=0;r<2;r++){
                int idx = tid + r*256; int p=idx>>5, c=idx&31;
                cpasync16(bb + p*BSTRIDE + c*16, getB16(kt+2, idx));
            }
        }
        asm volatile("cp.async.commit_group;" ::: "memory");
        asm volatile("cp.async.wait_group 2;" ::: "memory");
        __syncthreads();
        compute_tile(ab, ab + A_TILE, acc, wm, wn, gq, tq, lane);
    }
}

// ---- mainloop B: both operands via cp.async ----
template<class FA, class FB>
__device__ __forceinline__ void mainloop_cp(int nk, float (&acc)[4][4][4],
                                            char* sm, FA getA16, FB getB16){
    const int tid = threadIdx.x;
    const uint32_t smb = smem_u32(sm);
    const int lane=tid&31, warp=tid>>5;
    const int wm=(warp>>2)*64, wn=(warp&3)*32, gq=lane>>2, tq=lane&3;

    auto stage_loads = [&](int s){
        const uint32_t ab = smb + (s&3)*STAGE;
        const uint32_t bb = ab + A_TILE;
        #pragma unroll
        for(int r=0;r<2;r++){
            int idx = tid + r*256; int m=idx>>2, c=idx&3;
            cpasync16(ab + m*ASTRIDE + c*16, getA16(s, idx));
        }
        #pragma unroll
        for(int r=0;r<2;r++){
            int idx = tid + r*256; int p=idx>>5, c=idx&31;
            cpasync16(bb + p*BSTRIDE + c*16, getB16(s, idx));
        }
    };

    #pragma unroll
    for(int pg=0; pg<2; pg++){
        if(pg < nk) stage_loads(pg);
        asm volatile("cp.async.commit_group;" ::: "memory");
    }
    for(int kt=0; kt<nk; ++kt){
        if(kt+2 < nk) stage_loads(kt+2);
        asm volatile("cp.async.commit_group;" ::: "memory");
        asm volatile("cp.async.wait_group 2;" ::: "memory");
        __syncthreads();
        const uint32_t ab = smb + (kt&3)*STAGE;
        compute_tile(ab, ab + A_TILE, acc, wm, wn, gq, tq, lane);
    }
}

// ---- mainloop C: A = sum of two fp16 sources (LDG + HADD2 + STS), B via cp.async ----
template<class FA0, class FA1, class FB>
__device__ __forceinline__ void mainloop_sum(int nk, float (&acc)[4][4][4],
                                             char* sm, FA0 getA0, FA1 getA1, FB getB16){
    const int tid = threadIdx.x;
    const uint32_t smb = smem_u32(sm);
    const int lane=tid&31, warp=tid>>5;
    const int wm=(warp>>2)*64, wn=(warp&3)*32, gq=lane>>2, tq=lane&3;
    int am[2], ac[2];
    amap(tid,     am[0], ac[0]);
    amap(tid+256, am[1], ac[1]);

    auto cpB = [&](int s){
        const uint32_t bb = smb + (s&3)*STAGE + A_TILE;
        #pragma unroll
        for(int r=0;r<2;r++){
            int idx = tid + r*256; int p=idx>>5, c=idx&31;
            cpasync16(bb + p*BSTRIDE + c*16, getB16(s, idx));
        }
    };
    auto ldA = [&](int s, uint4 (*sv)[2]){
        #pragma unroll
        for(int r=0;r<2;r++){
            sv[r][0] = __ldg((const uint4*)getA0(s, am[r], ac[r]));
            sv[r][1] = __ldg((const uint4*)getA1(s, am[r], ac[r]));
        }
    };
    auto stA = [&](int s, uint4 (*sv)[2]){
        const uint32_t ab = smb + (s&3)*STAGE;
        #pragma unroll
        for(int r=0;r<2;r++){
            uint4 v;
            v.x = hadd2u(sv[r][0].x, sv[r][1].x);
            v.y = hadd2u(sv[r][0].y, sv[r][1].y);
            v.z = hadd2u(sv[r][0].z, sv[r][1].z);
            v.w = hadd2u(sv[r][0].w, sv[r][1].w);
            sts_u4(ab + am[r]*ASTRIDE + ac[r]*16, v);
        }
    };

    uint4 sv[2][2];
    ldA(0, sv);
    cpB(0); asm volatile("cp.async.commit_group;" ::: "memory");
    if(nk>1) cpB(1);
    asm volatile("cp.async.commit_group;" ::: "memory");

    for(int kt=0; kt<nk; ++kt){
        stA(kt, sv);
        if(kt+1 < nk) ldA(kt+1, sv);
        if(kt+2 < nk) cpB(kt+2);
        asm volatile("cp.async.commit_group;" ::: "memory");
        asm volatile("cp.async.wait_group 2;" ::: "memory");
        __syncthreads();
        const uint32_t ab = smb + (kt&3)*STAGE;
        compute_tile(ab, ab + A_TILE, acc, wm, wn, gq, tq, lane);
    }
}

// ---------------- prep ----------------
__global__ void prep_kernel(const float* __restrict__ xf, const float* __restrict__ mask,
                            const float* __restrict__ W,  const float* __restrict__ Wud,
                            const float* __restrict__ Wlr,const float* __restrict__ Wg){
    const int bx = blockIdx.x, tid = threadIdx.x;
    if(bx < 2048){
        int idx = bx*256 + tid;
        int p = idx >> 7, n4 = (idx & 127)*4;
        float4 v0 = *(const float4*)(xf + (size_t)(2*p)*DD + n4);
        float4 v1 = *(const float4*)(xf + (size_t)(2*p+1)*DD + n4);
        __half2 r0 = __floats2half2_rn(v0.x, v0.y), r1 = __floats2half2_rn(v0.z, v0.w);
        __half2 r2 = __floats2half2_rn(v1.x, v1.y), r3 = __floats2half2_rn(v1.z, v1.w);
        uint2 u0; u0.x=*(uint32_t*)&r0; u0.y=*(uint32_t*)&r1;
        uint2 u1; u1.x=*(uint32_t*)&r2; u1.y=*(uint32_t*)&r3;
        *(uint2*)(g_xfH + (size_t)(2*p)*DD + n4)   = u0;
        *(uint2*)(g_xfH + (size_t)(2*p+1)*DD + n4) = u1;
        __half2 p0 = __floats2half2_rn(v0.x, v1.x);
        __half2 p1 = __floats2half2_rn(v0.y, v1.y);
        __half2 p2 = __floats2half2_rn(v0.z, v1.z);
        __half2 p3 = __floats2half2_rn(v0.w, v1.w);
        uint4 up; up.x=*(uint32_t*)&p0; up.y=*(uint32_t*)&p1; up.z=*(uint32_t*)&p2; up.w=*(uint32_t*)&p3;
        *(uint4*)(g_xfP + (size_t)p*DD + n4) = up;
    } else if(bx < 4096){
        int i = bx - 2048;
        const float* src; __half2* dst;
        switch(i >> 9){
            case 0: src=W;   dst=g_WP;   break;
            case 1: src=Wud; dst=g_WudP; break;
            case 2: src=Wlr; dst=g_WlrP; break;
            default:src=Wg;  dst=g_WgP;  break;
        }
        int idx = (i & 511)*256 + tid;
        int p = idx >> 9, n = idx & 511;
        float2 v = *(const float2*)(src + (size_t)n*DD + 2*p);
        dst[(size_t)p*DD + n] = __floats2half2_rn(v.x, v.y);
    } else {
        __shared__ float red[256];
        float s=0.f;
        for(int i=tid;i<NROWS;i+=256) s += mask[i];
        red[tid]=s; __syncthreads();
        for(int st=128;st>0;st>>=1){
            if(tid<st) red[tid]+=red[tid+st];
            __syncthreads();
        }
        if(tid==0) g_nsum = red[0];
        g_pooled[tid]     = 0.f;
        g_pooled[tid+256] = 0.f;
    }
}

// ---------------- mega: half-K big aggregations + pool + y_x ----------------
// Big CTA map: col fastest (R9 win) so the 4 CTAs sharing an A row-slab co-reside.
__global__ void __launch_bounds__(256,2) mega_kernel(
        const float* __restrict__ a_ud, const float* __restrict__ a_lr,
        const float* __restrict__ b_g,  const float* __restrict__ mask){
    extern __shared__ char sm[];
    const int bx = blockIdx.x;
    const int lane=threadIdx.x&31, warp=threadIdx.x>>5;
    const int wm=(warp>>2)*64, wn=(warp&3)*32, gq=lane>>2, tq=lane&3;
    float acc[4][4][4]; ZERO_ACC(acc);

    if(bx < 1024){
        // mat(2) x half(2) x row(64) x col(4), col fastest
        const int mat = bx>>9, half = (bx>>8)&1, row = (bx>>2)&63, col = bx&3;
        const float* A = mat ? a_lr : a_ud;
        __half* C = g_hp + (size_t)(mat*2 + half)*HP_SZ;
        const size_t rowBase = (size_t)row * BM;
        const int colBase = col * BN;
        const int kOff = half * 4096;
        auto getAf4=[&](int s,int idx){
            int m=idx>>3, c=idx&7;
            return (const float4*)(A + (rowBase+m)*NROWS + kOff + s*BK + c*4);
        };
        auto getB16=[&](int s,int idx){
            int p=idx>>5, c=idx&31;
            return (const void*)(g_xfP + (size_t)(kOff/2 + s*16 + p)*DD + colBase + c*4);
        };
        mainloop_conv(4096/BK, acc, sm, getAf4, getB16);
        #pragma unroll
        for(int mt=0;mt<4;mt++){
            size_t r0 = rowBase + wm + mt*16 + gq;
            #pragma unroll
            for(int nt=0;nt<4;nt++){
                int c0 = colBase + wn + nt*8 + 2*tq;
                *(__half2*)(C + r0*DD + c0)     = __floats2half2_rn(acc[mt][nt][0], acc[mt][nt][1]);
                *(__half2*)(C + (r0+8)*DD + c0) = __floats2half2_rn(acc[mt][nt][2], acc[mt][nt][3]);
            }
        }
    } else if(bx < 1280){
        const int i = bx - 1024;
        const size_t rowBase = (size_t)(i & 63) * BM;
        const int colBase = (i >> 6) * BN;
        auto getA16=[&](int s,int idx){
            int m=idx>>2, c=idx&3;
            return (const void*)(g_xfH + (rowBase+m)*DD + s*BK + c*8);
        };
        auto getB16=[&](int s,int idx){
            int p=idx>>5, c=idx&31;
            return (const void*)(g_WgP + (size_t)(s*16+p)*DD + colBase + c*4);
        };
        mainloop_cp(DD/BK, acc, sm, getA16, getB16);
        float cs[4][2];
        #pragma unroll
        for(int nt=0;nt<4;nt++){ cs[nt][0]=0.f; cs[nt][1]=0.f; }
        #pragma unroll
        for(int mt=0;mt<4;mt++){
            size_t r0 = rowBase + wm + mt*16 + gq;
            float m0 = mask[r0], m8 = mask[r0+8];
            #pragma unroll
            for(int nt=0;nt<4;nt++){
                int c0 = colBase + wn + nt*8 + 2*tq;
                float bg0 = b_g[c0], bg1 = b_g[c0+1];
                cs[nt][0] += fmaxf(acc[mt][nt][0]+bg0,0.f)*m0 + fmaxf(acc[mt][nt][2]+bg0,0.f)*m8;
                cs[nt][1] += fmaxf(acc[mt][nt][1]+bg1,0.f)*m0 + fmaxf(acc[mt][nt][3]+bg1,0.f)*m8;
            }
        }
        #pragma unroll
        for(int nt=0;nt<4;nt++){
            #pragma unroll
            for(int j=0;j<2;j++){
                float v = cs[nt][j];
                v += __shfl_xor_sync(0xffffffffu, v, 4);
                v += __shfl_xor_sync(0xffffffffu, v, 8);
                v += __shfl_xor_sync(0xffffffffu, v, 16);
                if(lane < 4)
                    atomicAdd(&g_pooled[colBase + wn + nt*8 + 2*tq + j], v);
            }
        }
    } else {
        const int i = bx - 1280;
        const size_t rowBase = (size_t)(i & 63) * BM;
        const int colBase = (i >> 6) * BN;
        auto getA16=[&](int s,int idx){
            int m=idx>>2, c=idx&3;
            return (const void*)(g_xfH + (rowBase+m)*DD + s*BK + c*8);
        };
        auto getB16=[&](int s,int idx){
            int p=idx>>5, c=idx&31;
            return (const void*)(g_WP + (size_t)(s*16+p)*DD + colBase + c*4);
        };
        mainloop_cp(DD/BK, acc, sm, getA16, getB16);
        #pragma unroll
        for(int mt=0;mt<4;mt++){
            size_t r0 = rowBase + wm + mt*16 + gq;
            #pragma unroll
            for(int nt=0;nt<4;nt++){
                int c0 = colBase + wn + nt*8 + 2*tq;
                *(__half2*)(g_yx + r0*DD + c0)     = __floats2half2_rn(acc[mt][nt][0], acc[mt][nt][1]);
                *(__half2*)(g_yx + (r0+8)*DD + c0) = __floats2half2_rn(acc[mt][nt][2], acc[mt][nt][3]);
            }
        }
    }
}

// ---------------- final: h = relu( y_x + h_ud@Wud^T + h_lr@Wlr^T + bias ) ----------------
__global__ void __launch_bounds__(256,2) final_kernel(
        const float* __restrict__ W_go,
        const float* __restrict__ b,   const float* __restrict__ b_ud,
        const float* __restrict__ b_lr,const float* __restrict__ b_go,
        float* __restrict__ out){
    extern __shared__ char sm[];
    float* hg    = (float*)(sm + HG_OFF);
    float* sbias = (float*)(sm + SB_OFF);
    const int tid = threadIdx.x;
    const size_t rowBase = (size_t)(blockIdx.x & 63) * BM;
    const int colBase = (blockIdx.x >> 6) * BN;

    {
        float inv = 1.0f / g_nsum;
        hg[tid]     = g_pooled[tid]*inv;
        hg[tid+256] = g_pooled[tid+256]*inv;
    }
    __syncthreads();
    if(blockIdx.x == 0){
        out[HP_SZ + tid]       = hg[tid];
        out[HP_SZ + tid + 256] = hg[tid+256];
    }
    {
        int j = colBase + (tid>>1);
        int k0 = (tid&1)*256;
        const float4* wr = (const float4*)(W_go + (size_t)j*DD + k0);
        float s = 0.f;
        #pragma unroll 8
        for(int q=0;q<64;q++){
            float4 wv = wr[q];
            s += hg[k0+4*q]*wv.x + hg[k0+4*q+1]*wv.y + hg[k0+4*q+2]*wv.z + hg[k0+4*q+3]*wv.w;
        }
        s += __shfl_xor_sync(0xffffffffu, s, 1);
        if((tid&1)==0) sbias[tid>>1] = s + b[j] + b_ud[j] + b_lr[j] + b_go[j];
    }
    __syncthreads();

    float acc[4][4][4]; ZERO_ACC(acc);
    // K=1024: seg 0 = h_ud (partials 0,1), seg 1 = h_lr (partials 2,3)
    auto getA0=[&](int s,int m,int c){
        int seg = s>>4;
        const __half* A = g_hp + (size_t)(seg*2)*HP_SZ;
        return (const void*)(A + (rowBase+m)*DD + (s&15)*BK + c*8);
    };
    auto getA1=[&](int s,int m,int c){
        int seg = s>>4;
        const __half* A = g_hp + (size_t)(seg*2+1)*HP_SZ;
        return (const void*)(A + (rowBase+m)*DD + (s&15)*BK + c*8);
    };
    auto getB16=[&](int s,int idx){
        int p=idx>>5, c=idx&31; int seg=s>>4;
        const __half2* B = seg ? g_WlrP : g_WudP;
        return (const void*)(B + (size_t)((s&15)*16+p)*DD + colBase + c*4);
    };
    mainloop_sum(2*DD/BK, acc, sm, getA0, getA1, getB16);

    const int lane=tid&31, warp=tid>>5;
    const int wm=(warp>>2)*64, wn=(warp&3)*32, gq=lane>>2, tq=lane&3;
    #pragma unroll
    for(int mt=0;mt<4;mt++){
        size_t r0 = rowBase + wm + mt*16 + gq;
        #pragma unroll
        for(int nt=0;nt<4;nt++){
            int c0 = colBase + wn + nt*8 + 2*tq;
            float bb0 = sbias[c0-colBase], bb1 = sbias[c0-colBase+1];
            float2 y0 = __half22float2(*(const __half2*)(g_yx + r0*DD + c0));
            float2 y2 = __half22float2(*(const __half2*)(g_yx + (r0+8)*DD + c0));
            float2 v0 = make_float2(fmaxf(acc[mt][nt][0]+y0.x+bb0,0.f),
                                    fmaxf(acc[mt][nt][1]+y0.y+bb1,0.f));
            float2 v2 = make_float2(fmaxf(acc[mt][nt][2]+y2.x+bb0,0.f),
                                    fmaxf(acc[mt][nt][3]+y2.y+bb1,0.f));
            *(float2*)(out + r0*DD + c0)     = v0;
            *(float2*)(out + (r0+8)*DD + c0) = v2;
        }
    }
}

// ---------------- launch ----------------
extern "C" void kernel_launch(void* const* d_in, const int* in_sizes, int n_in,
                              void* d_out, int out_size){
    const float* x    = (const float*)d_in[0];
    const float* mask = (const float*)d_in[1];
    const float* a_ud = (const float*)d_in[2];
    const float* a_lr = (const float*)d_in[3];
    const float* W    = (const float*)d_in[4];
    const float* b    = (const float*)d_in[5];
    const float* W_ud = (const float*)d_in[6];
    const float* b_ud = (const float*)d_in[7];
    const float* W_lr = (const float*)d_in[8];
    const float* b_lr = (const float*)d_in[9];
    const float* W_g  = (const float*)d_in[10];
    const float* b_g  = (const float*)d_in[11];
    const float* W_go = (const float*)d_in[12];
    const float* b_go = (const float*)d_in[13];
    float* out = (float*)d_out;

    cudaFuncSetAttribute(mega_kernel,  cudaFuncAttributeMaxDynamicSharedMemorySize, SMEM_TOTAL);
    cudaFuncSetAttribute(final_kernel, cudaFuncAttributeMaxDynamicSharedMemorySize, FINAL_SMEM);

    prep_kernel<<<4097, 256>>>(x, mask, W, W_ud, W_lr, W_g);
    mega_kernel<<<1536, 256, SMEM_TOTAL>>>(a_ud, a_lr, b_g, mask);
    final_kernel<<<256, 256, FINAL_SMEM>>>(W_go, b, b_ud, b_lr, b_go, out);
}

// round 16
// speedup vs baseline: 1.5389x; 1.0078x over previous
#include <cuda_runtime.h>
#include <cuda_fp16.h>
#include <cstdint>

#define NROWS 8192
#define DD    512

// GEMM tile: BM=128, BN=128, BK=32, 256 threads, warp grid 2(m) x 4(n), warp tile 64x32
#define BM 128
#define BN 128
#define BK 32
#define ASTRIDE 80                 // bytes per A smem row (32 halves + pad); LDSM conflict-free
#define BSTRIDE 544                // bytes per B smem pair-row; conflict-free
#define A_TILE (BM*ASTRIDE)        // 10240
#define B_TILE ((BK/2)*BSTRIDE)    // 8704
#define STAGE  (A_TILE + B_TILE)   // 18944
#define NSTAGE 4
#define SMEM_TOTAL (NSTAGE*STAGE)  // 75776
#define HG_OFF   SMEM_TOTAL
#define SB_OFF   (HG_OFF + DD*4)
#define FINAL_SMEM (SB_OFF + 128*4)

#define HP_SZ ((size_t)NROWS*DD)

// ---------------- device scratch ----------------
__device__ __half  g_xfH[NROWS*DD];      // xf fp16 row-major
__device__ __half2 g_xfP[(NROWS/2)*DD];  // xf k-pair-packed [k/2][n]
__device__ __half  g_hp[4*NROWS*DD];     // partials: [mat(2)][kh(2)] half-K results
__device__ __half  g_yx[NROWS*DD];       // xf @ W^T, fp16
__device__ __half2 g_WP  [(DD/2)*DD];
__device__ __half2 g_WudP[(DD/2)*DD];
__device__ __half2 g_WlrP[(DD/2)*DD];
__device__ __half2 g_WgP [(DD/2)*DD];
__device__ float   g_pooled[DD];
__device__ float   g_nsum;

// ---------------- helpers ----------------
__device__ __forceinline__ uint32_t smem_u32(const void* p){
    return (uint32_t)__cvta_generic_to_shared(p);
}
__device__ __forceinline__ void cpasync16(uint32_t s, const void* g){
    asm volatile("cp.async.cg.shared.global [%0], [%1], 16;\n" :: "r"(s), "l"(g));
}
__device__ __forceinline__ void hmma(float* c, const uint32_t a[4], const uint32_t b[2]){
    asm volatile(
      "mma.sync.aligned.m16n8k16.row.col.f32.f16.f16.f32 "
      "{%0,%1,%2,%3},{%4,%5,%6,%7},{%8,%9},{%0,%1,%2,%3};\n"
      : "+f"(c[0]),"+f"(c[1]),"+f"(c[2]),"+f"(c[3])
      : "r"(a[0]),"r"(a[1]),"r"(a[2]),"r"(a[3]),"r"(b[0]),"r"(b[1]));
}
__device__ __forceinline__ void ldsm4(uint32_t* r, uint32_t addr){
    asm volatile("ldmatrix.sync.aligned.m8n8.x4.shared.b16 {%0,%1,%2,%3}, [%4];"
        : "=r"(r[0]),"=r"(r[1]),"=r"(r[2]),"=r"(r[3]) : "r"(addr));
}
__device__ __forceinline__ uint32_t lds32(uint32_t addr){
    uint32_t v; asm volatile("ld.shared.b32 %0, [%1];" : "=r"(v) : "r"(addr)); return v;
}
__device__ __forceinline__ void sts_u2(uint32_t addr, uint32_t x, uint32_t y){
    asm volatile("st.shared.v2.b32 [%0], {%1,%2};" :: "r"(addr), "r"(x), "r"(y));
}
__device__ __forceinline__ void sts_u4(uint32_t addr, uint4 v){
    asm volatile("st.shared.v4.b32 [%0], {%1,%2,%3,%4};"
        :: "r"(addr), "r"(v.x), "r"(v.y), "r"(v.z), "r"(v.w));
}
__device__ __forceinline__ uint32_t hadd2u(uint32_t a, uint32_t b){
    __half2 r = __hadd2(*(__half2*)&a, *(__half2*)&b); return *(uint32_t*)&r;
}
// conflict-free A-chunk mapping for 16B STS at ASTRIDE=80
__device__ __forceinline__ void amap(int idx, int& m, int& c){
    int q = idx>>2; c = idx&3;
    m = (q & 0x78) | ((q & 1) << 2) | ((q >> 1) & 3);
}

#define ZERO_ACC(acc) do{ _Pragma("unroll") for(int i_=0;i_<4;i_++) \
    _Pragma("unroll") for(int j_=0;j_<4;j_++) \
    _Pragma("unroll") for(int q_=0;q_<4;q_++) acc[i_][j_][q_]=0.f; }while(0)

// One BK=32 tile of MMAs. A via ldmatrix.x4, B via LDS.32.
__device__ __forceinline__ void compute_tile(uint32_t As, uint32_t Bs,
                                             float (&acc)[4][4][4],
                                             int wm,int wn,int gq,int tq,int lane){
    const uint32_t arow = lane & 15;
    const uint32_t acol = (lane >> 4) * 16;
    const uint32_t abase = As + (wm + arow)*ASTRIDE + acol;
    const uint32_t bbase = Bs + tq*BSTRIDE + (wn + gq)*4;
    #pragma unroll
    for(int kk=0;kk<2;kk++){
        uint32_t a[4][4], b[4][2];
        #pragma unroll
        for(int mt=0;mt<4;mt++)
            ldsm4(a[mt], abase + mt*16*ASTRIDE + kk*32);
        #pragma unroll
        for(int nt=0;nt<4;nt++){
            uint32_t p = bbase + kk*8*BSTRIDE + nt*32;
            b[nt][0] = lds32(p);
            b[nt][1] = lds32(p + 4*BSTRIDE);
        }
        #pragma unroll
        for(int mt=0;mt<4;mt++)
            #pragma unroll
            for(int nt=0;nt<4;nt++)
                hmma(acc[mt][nt], a[mt], b[nt]);
    }
}

// ---- mainloop A: A fp32 global, converted in-flight ----
template<class FA, class FB>
__device__ __forceinline__ void mainloop_conv(int nk, float (&acc)[4][4][4],
                                              char* sm, FA getAf4, FB getB16){
    const int tid = threadIdx.x;
    const uint32_t smb = smem_u32(sm);
    const int lane=tid&31, warp=tid>>5;
    const int wm=(warp>>2)*64, wn=(warp&3)*32, gq=lane>>2, tq=lane&3;

    float4 av[4];
    #pragma unroll
    for(int r=0;r<4;r++) av[r] = __ldg(getAf4(0, tid + r*256));

    #pragma unroll
    for(int pg=0; pg<2; pg++){
        if(pg < nk){
            const uint32_t bb = smb + pg*STAGE + A_TILE;
            #pragma unroll
            for(int r=0;r<2;r++){
                int idx = tid + r*256; int p=idx>>5, c=idx&31;
                cpasync16(bb + p*BSTRIDE + c*16, getB16(pg, idx));
            }
        }
        asm volatile("cp.async.commit_group;" ::: "memory");
    }

    for(int kt=0; kt<nk; ++kt){
        const uint32_t ab = smb + (kt&3)*STAGE;
        #pragma unroll
        for(int r=0;r<4;r++){
            int idx = tid + r*256; int m=idx>>3, c=idx&7;
            __half2 h0 = __floats2half2_rn(av[r].x, av[r].y);
            __half2 h1 = __floats2half2_rn(av[r].z, av[r].w);
            sts_u2(ab + m*ASTRIDE + c*8, *(uint32_t*)&h0, *(uint32_t*)&h1);
        }
        if(kt+1 < nk){
            #pragma unroll
            for(int r=0;r<4;r++) av[r] = __ldg(getAf4(kt+1, tid + r*256));
        }
        if(kt+2 < nk){
            const uint32_t bb = smb + ((kt+2)&3)*STAGE + A_TILE;
            #pragma unroll
            for(int r=0;r<2;r++){
                int idx = tid + r*256; int p=idx>>5, c=idx&31;
                cpasync16(bb + p*BSTRIDE + c*16, getB16(kt+2, idx));
            }
        }
        asm volatile("cp.async.commit_group;" ::: "memory");
        asm volatile("cp.async.wait_group 2;" ::: "memory");
        __syncthreads();
        compute_tile(ab, ab + A_TILE, acc, wm, wn, gq, tq, lane);
    }
}

// ---- mainloop B: both operands via cp.async ----
template<class FA, class FB>
__device__ __forceinline__ void mainloop_cp(int nk, float (&acc)[4][4][4],
                                            char* sm, FA getA16, FB getB16){
    const int tid = threadIdx.x;
    const uint32_t smb = smem_u32(sm);
    const int lane=tid&31, warp=tid>>5;
    const int wm=(warp>>2)*64, wn=(warp&3)*32, gq=lane>>2, tq=lane&3;

    auto stage_loads = [&](int s){
        const uint32_t ab = smb + (s&3)*STAGE;
        const uint32_t bb = ab + A_TILE;
        #pragma unroll
        for(int r=0;r<2;r++){
            int idx = tid + r*256; int m=idx>>2, c=idx&3;
            cpasync16(ab + m*ASTRIDE + c*16, getA16(s, idx));
        }
        #pragma unroll
        for(int r=0;r<2;r++){
            int idx = tid + r*256; int p=idx>>5, c=idx&31;
            cpasync16(bb + p*BSTRIDE + c*16, getB16(s, idx));
        }
    };

    #pragma unroll
    for(int pg=0; pg<2; pg++){
        if(pg < nk) stage_loads(pg);
        asm volatile("cp.async.commit_group;" ::: "memory");
    }
    for(int kt=0; kt<nk; ++kt){
        if(kt+2 < nk) stage_loads(kt+2);
        asm volatile("cp.async.commit_group;" ::: "memory");
        asm volatile("cp.async.wait_group 2;" ::: "memory");
        __syncthreads();
        const uint32_t ab = smb + (kt&3)*STAGE;
        compute_tile(ab, ab + A_TILE, acc, wm, wn, gq, tq, lane);
    }
}

// ---- mainloop C: A = sum of two fp16 sources (LDG + HADD2 + STS), B via cp.async ----
template<class FA0, class FA1, class FB>
__device__ __forceinline__ void mainloop_sum(int nk, float (&acc)[4][4][4],
                                             char* sm, FA0 getA0, FA1 getA1, FB getB16){
    const int tid = threadIdx.x;
    const uint32_t smb = smem_u32(sm);
    const int lane=tid&31, warp=tid>>5;
    const int wm=(warp>>2)*64, wn=(warp&3)*32, gq=lane>>2, tq=lane&3;
    int am[2], ac[2];
    amap(tid,     am[0], ac[0]);
    amap(tid+256, am[1], ac[1]);

    auto cpB = [&](int s){
        const uint32_t bb = smb + (s&3)*STAGE + A_TILE;
        #pragma unroll
        for(int r=0;r<2;r++){
            int idx = tid + r*256; int p=idx>>5, c=idx&31;
            cpasync16(bb + p*BSTRIDE + c*16, getB16(s, idx));
        }
    };
    auto ldA = [&](int s, uint4 (*sv)[2]){
        #pragma unroll
        for(int r=0;r<2;r++){
            sv[r][0] = __ldg((const uint4*)getA0(s, am[r], ac[r]));
            sv[r][1] = __ldg((const uint4*)getA1(s, am[r], ac[r]));
        }
    };
    auto stA = [&](int s, uint4 (*sv)[2]){
        const uint32_t ab = smb + (s&3)*STAGE;
        #pragma unroll
        for(int r=0;r<2;r++){
            uint4 v;
            v.x = hadd2u(sv[r][0].x, sv[r][1].x);
            v.y = hadd2u(sv[r][0].y, sv[r][1].y);
            v.z = hadd2u(sv[r][0].z, sv[r][1].z);
            v.w = hadd2u(sv[r][0].w, sv[r][1].w);
            sts_u4(ab + am[r]*ASTRIDE + ac[r]*16, v);
        }
    };

    uint4 sv[2][2];
    ldA(0, sv);
    cpB(0); asm volatile("cp.async.commit_group;" ::: "memory");
    if(nk>1) cpB(1);
    asm volatile("cp.async.commit_group;" ::: "memory");

    for(int kt=0; kt<nk; ++kt){
        stA(kt, sv);
        if(kt+1 < nk) ldA(kt+1, sv);
        if(kt+2 < nk) cpB(kt+2);
        asm volatile("cp.async.commit_group;" ::: "memory");
        asm volatile("cp.async.wait_group 2;" ::: "memory");
        __syncthreads();
        const uint32_t ab = smb + (kt&3)*STAGE;
        compute_tile(ab, ab + A_TILE, acc, wm, wn, gq, tq, lane);
    }
}

// ---------------- prep ----------------
__global__ void prep_kernel(const float* __restrict__ xf, const float* __restrict__ mask,
                            const float* __restrict__ W,  const float* __restrict__ Wud,
                            const float* __restrict__ Wlr,const float* __restrict__ Wg){
    const int bx = blockIdx.x, tid = threadIdx.x;
    if(bx < 2048){
        int idx = bx*256 + tid;
        int p = idx >> 7, n4 = (idx & 127)*4;
        float4 v0 = *(const float4*)(xf + (size_t)(2*p)*DD + n4);
        float4 v1 = *(const float4*)(xf + (size_t)(2*p+1)*DD + n4);
        __half2 r0 = __floats2half2_rn(v0.x, v0.y), r1 = __floats2half2_rn(v0.z, v0.w);
        __half2 r2 = __floats2half2_rn(v1.x, v1.y), r3 = __floats2half2_rn(v1.z, v1.w);
        uint2 u0; u0.x=*(uint32_t*)&r0; u0.y=*(uint32_t*)&r1;
        uint2 u1; u1.x=*(uint32_t*)&r2; u1.y=*(uint32_t*)&r3;
        *(uint2*)(g_xfH + (size_t)(2*p)*DD + n4)   = u0;
        *(uint2*)(g_xfH + (size_t)(2*p+1)*DD + n4) = u1;
        __half2 p0 = __floats2half2_rn(v0.x, v1.x);
        __half2 p1 = __floats2half2_rn(v0.y, v1.y);
        __half2 p2 = __floats2half2_rn(v0.z, v1.z);
        __half2 p3 = __floats2half2_rn(v0.w, v1.w);
        uint4 up; up.x=*(uint32_t*)&p0; up.y=*(uint32_t*)&p1; up.z=*(uint32_t*)&p2; up.w=*(uint32_t*)&p3;
        *(uint4*)(g_xfP + (size_t)p*DD + n4) = up;
    } else if(bx < 4096){
        int i = bx - 2048;
        const float* src; __half2* dst;
        switch(i >> 9){
            case 0: src=W;   dst=g_WP;   break;
            case 1: src=Wud; dst=g_WudP; break;
            case 2: src=Wlr; dst=g_WlrP; break;
            default:src=Wg;  dst=g_WgP;  break;
        }
        int idx = (i & 511)*256 + tid;
        int p = idx >> 9, n = idx & 511;
        float2 v = *(const float2*)(src + (size_t)n*DD + 2*p);
        dst[(size_t)p*DD + n] = __floats2half2_rn(v.x, v.y);
    } else {
        __shared__ float red[256];
        float s=0.f;
        for(int i=tid;i<NROWS;i+=256) s += mask[i];
        red[tid]=s; __syncthreads();
        for(int st=128;st>0;st>>=1){
            if(tid<st) red[tid]+=red[tid+st];
            __syncthreads();
        }
        if(tid==0) g_nsum = red[0];
        g_pooled[tid]     = 0.f;
        g_pooled[tid+256] = 0.f;
    }
}

// ---------------- mega: half-K big aggregations + pool + y_x ----------------
// Big CTA map: col fastest (R9 win) so the 4 CTAs sharing an A row-slab co-reside.
__global__ void __launch_bounds__(256,2) mega_kernel(
        const float* __restrict__ a_ud, const float* __restrict__ a_lr,
        const float* __restrict__ b_g,  const float* __restrict__ mask){
    extern __shared__ char sm[];
    const int bx = blockIdx.x;
    const int lane=threadIdx.x&31, warp=threadIdx.x>>5;
    const int wm=(warp>>2)*64, wn=(warp&3)*32, gq=lane>>2, tq=lane&3;
    float acc[4][4][4]; ZERO_ACC(acc);

    if(bx < 1024){
        // mat(2) x half(2) x row(64) x col(4), col fastest
        const int mat = bx>>9, half = (bx>>8)&1, row = (bx>>2)&63, col = bx&3;
        const float* A = mat ? a_lr : a_ud;
        __half* C = g_hp + (size_t)(mat*2 + half)*HP_SZ;
        const size_t rowBase = (size_t)row * BM;
        const int colBase = col * BN;
        const int kOff = half * 4096;
        auto getAf4=[&](int s,int idx){
            int m=idx>>3, c=idx&7;
            return (const float4*)(A + (rowBase+m)*NROWS + kOff + s*BK + c*4);
        };
        auto getB16=[&](int s,int idx){
            int p=idx>>5, c=idx&31;
            return (const void*)(g_xfP + (size_t)(kOff/2 + s*16 + p)*DD + colBase + c*4);
        };
        mainloop_conv(4096/BK, acc, sm, getAf4, getB16);
        #pragma unroll
        for(int mt=0;mt<4;mt++){
            size_t r0 = rowBase + wm + mt*16 + gq;
            #pragma unroll
            for(int nt=0;nt<4;nt++){
                int c0 = colBase + wn + nt*8 + 2*tq;
                *(__half2*)(C + r0*DD + c0)     = __floats2half2_rn(acc[mt][nt][0], acc[mt][nt][1]);
                *(__half2*)(C + (r0+8)*DD + c0) = __floats2half2_rn(acc[mt][nt][2], acc[mt][nt][3]);
            }
        }
    } else if(bx < 1280){
        const int i = bx - 1024;
        const size_t rowBase = (size_t)(i & 63) * BM;
        const int colBase = (i >> 6) * BN;
        auto getA16=[&](int s,int idx){
            int m=idx>>2, c=idx&3;
            return (const void*)(g_xfH + (rowBase+m)*DD + s*BK + c*8);
        };
        auto getB16=[&](int s,int idx){
            int p=idx>>5, c=idx&31;
            return (const void*)(g_WgP + (size_t)(s*16+p)*DD + colBase + c*4);
        };
        mainloop_cp(DD/BK, acc, sm, getA16, getB16);
        float cs[4][2];
        #pragma unroll
        for(int nt=0;nt<4;nt++){ cs[nt][0]=0.f; cs[nt][1]=0.f; }
        #pragma unroll
        for(int mt=0;mt<4;mt++){
            size_t r0 = rowBase + wm + mt*16 + gq;
            float m0 = mask[r0], m8 = mask[r0+8];
            #pragma unroll
            for(int nt=0;nt<4;nt++){
                int c0 = colBase + wn + nt*8 + 2*tq;
                float bg0 = b_g[c0], bg1 = b_g[c0+1];
                cs[nt][0] += fmaxf(acc[mt][nt][0]+bg0,0.f)*m0 + fmaxf(acc[mt][nt][2]+bg0,0.f)*m8;
                cs[nt][1] += fmaxf(acc[mt][nt][1]+bg1,0.f)*m0 + fmaxf(acc[mt][nt][3]+bg1,0.f)*m8;
            }
        }
        #pragma unroll
        for(int nt=0;nt<4;nt++){
            #pragma unroll
            for(int j=0;j<2;j++){
                float v = cs[nt][j];
                v += __shfl_xor_sync(0xffffffffu, v, 4);
                v += __shfl_xor_sync(0xffffffffu, v, 8);
                v += __shfl_xor_sync(0xffffffffu, v, 16);
                if(lane < 4)
                    atomicAdd(&g_pooled[colBase + wn + nt*8 + 2*tq + j], v);
            }
        }
    } else {
        const int i = bx - 1280;
        const size_t rowBase = (size_t)(i & 63) * BM;
        const int colBase = (i >> 6) * BN;
        auto getA16=[&](int s,int idx){
            int m=idx>>2, c=idx&3;
            return (const void*)(g_xfH + (rowBase+m)*DD + s*BK + c*8);
        };
        auto getB16=[&](int s,int idx){
            int p=idx>>5, c=idx&31;
            return (const void*)(g_WP + (size_t)(s*16+p)*DD + colBase + c*4);
        };
        mainloop_cp(DD/BK, acc, sm, getA16, getB16);
        #pragma unroll
        for(int mt=0;mt<4;mt++){
            size_t r0 = rowBase + wm + mt*16 + gq;
            #pragma unroll
            for(int nt=0;nt<4;nt++){
                int c0 = colBase + wn + nt*8 + 2*tq;
                *(__half2*)(g_yx + r0*DD + c0)     = __floats2half2_rn(acc[mt][nt][0], acc[mt][nt][1]);
                *(__half2*)(g_yx + (r0+8)*DD + c0) = __floats2half2_rn(acc[mt][nt][2], acc[mt][nt][3]);
            }
        }
    }
}

// ---------------- final: h = relu( y_x + h_ud@Wud^T + h_lr@Wlr^T + bias ) ----------------
__global__ void __launch_bounds__(256,2) final_kernel(
        const float* __restrict__ W_go,
        const float* __restrict__ b,   const float* __restrict__ b_ud,
        const float* __restrict__ b_lr,const float* __restrict__ b_go,
        float* __restrict__ out){
    extern __shared__ char sm[];
    float* hg    = (float*)(sm + HG_OFF);
    float* sbias = (float*)(sm + SB_OFF);
    const int tid = threadIdx.x;
    const size_t rowBase = (size_t)(blockIdx.x & 63) * BM;
    const int colBase = (blockIdx.x >> 6) * BN;

    {
        float inv = 1.0f / g_nsum;
        hg[tid]     = g_pooled[tid]*inv;
        hg[tid+256] = g_pooled[tid+256]*inv;
    }
    __syncthreads();
    if(blockIdx.x == 0){
        out[HP_SZ + tid]       = hg[tid];
        out[HP_SZ + tid + 256] = hg[tid+256];
    }
    {
        int j = colBase + (tid>>1);
        int k0 = (tid&1)*256;
        const float4* wr = (const float4*)(W_go + (size_t)j*DD + k0);
        float s = 0.f;
        #pragma unroll 8
        for(int q=0;q<64;q++){
            float4 wv = wr[q];
            s += hg[k0+4*q]*wv.x + hg[k0+4*q+1]*wv.y + hg[k0+4*q+2]*wv.z + hg[k0+4*q+3]*wv.w;
        }
        s += __shfl_xor_sync(0xffffffffu, s, 1);
        if((tid&1)==0) sbias[tid>>1] = s + b[j] + b_ud[j] + b_lr[j] + b_go[j];
    }
    __syncthreads();

    float acc[4][4][4]; ZERO_ACC(acc);
    // K=1024: seg 0 = h_ud (partials 0,1), seg 1 = h_lr (partials 2,3)
    auto getA0=[&](int s,int m,int c){
        int seg = s>>4;
        const __half* A = g_hp + (size_t)(seg*2)*HP_SZ;
        return (const void*)(A + (rowBase+m)*DD + (s&15)*BK + c*8);
    };
    auto getA1=[&](int s,int m,int c){
        int seg = s>>4;
        const __half* A = g_hp + (size_t)(seg*2+1)*HP_SZ;
        return (const void*)(A + (rowBase+m)*DD + (s&15)*BK + c*8);
    };
    auto getB16=[&](int s,int idx){
        int p=idx>>5, c=idx&31; int seg=s>>4;
        const __half2* B = seg ? g_WlrP : g_WudP;
        return (const void*)(B + (size_t)((s&15)*16+p)*DD + colBase + c*4);
    };
    mainloop_sum(2*DD/BK, acc, sm, getA0, getA1, getB16);

    const int lane=tid&31, warp=tid>>5;
    const int wm=(warp>>2)*64, wn=(warp&3)*32, gq=lane>>2, tq=lane&3;
    #pragma unroll
    for(int mt=0;mt<4;mt++){
        size_t r0 = rowBase + wm + mt*16 + gq;
        #pragma unroll
        for(int nt=0;nt<4;nt++){
            int c0 = colBase + wn + nt*8 + 2*tq;
            float bb0 = sbias[c0-colBase], bb1 = sbias[c0-colBase+1];
            float2 y0 = __half22float2(*(const __half2*)(g_yx + r0*DD + c0));
            float2 y2 = __half22float2(*(const __half2*)(g_yx + (r0+8)*DD + c0));
            float2 v0 = make_float2(fmaxf(acc[mt][nt][0]+y0.x+bb0,0.f),
                                    fmaxf(acc[mt][nt][1]+y0.y+bb1,0.f));
            float2 v2 = make_float2(fmaxf(acc[mt][nt][2]+y2.x+bb0,0.f),
                                    fmaxf(acc[mt][nt][3]+y2.y+bb1,0.f));
            *(float2*)(out + r0*DD + c0)     = v0;
            *(float2*)(out + (r0+8)*DD + c0) = v2;
        }
    }
}

// ---------------- launch ----------------
extern "C" void kernel_launch(void* const* d_in, const int* in_sizes, int n_in,
                              void* d_out, int out_size){
    const float* x    = (const float*)d_in[0];
    const float* mask = (const float*)d_in[1];
    const float* a_ud = (const float*)d_in[2];
    const float* a_lr = (const float*)d_in[3];
    const float* W    = (const float*)d_in[4];
    const float* b    = (const float*)d_in[5];
    const float* W_ud = (const float*)d_in[6];
    const float* b_ud = (const float*)d_in[7];
    const float* W_lr = (const float*)d_in[8];
    const float* b_lr = (const float*)d_in[9];
    const float* W_g  = (const float*)d_in[10];
    const float* b_g  = (const float*)d_in[11];
    const float* W_go = (const float*)d_in[12];
    const float* b_go = (const float*)d_in[13];
    float* out = (float*)d_out;

    cudaFuncSetAttribute(mega_kernel,  cudaFuncAttributeMaxDynamicSharedMemorySize, SMEM_TOTAL);
    cudaFuncSetAttribute(final_kernel, cudaFuncAttributeMaxDynamicSharedMemorySize, FINAL_SMEM);

    prep_kernel<<<4097, 256>>>(x, mask, W, W_ud, W_lr, W_g);
    mega_kernel<<<1536, 256, SMEM_TOTAL>>>(a_ud, a_lr, b_g, mask);
    final_kernel<<<256, 256, FINAL_SMEM>>>(W_go, b, b_ud, b_lr, b_go, out);
}

// round 17
// speedup vs baseline: 1.5390x; 1.0001x over previous
#include <cuda_runtime.h>
#include <cuda_fp16.h>
#include <cstdint>

#define NROWS 8192
#define DD    512

// GEMM tile: BM=128, BN=128, BK=32, 256 threads, warp grid 2(m) x 4(n), warp tile 64x32
#define BM 128
#define BN 128
#define BK 32
#define ASTRIDE 80                 // bytes per A smem row (32 halves + pad); LDSM conflict-free
#define BSTRIDE 544                // bytes per B smem pair-row; conflict-free
#define A_TILE (BM*ASTRIDE)        // 10240
#define B_TILE ((BK/2)*BSTRIDE)    // 8704
#define STAGE  (A_TILE + B_TILE)   // 18944
#define NSTAGE 4
#define SMEM_TOTAL (NSTAGE*STAGE)  // 75776
#define HG_OFF   SMEM_TOTAL
#define SB_OFF   (HG_OFF + DD*4)
#define FINAL_SMEM (SB_OFF + 128*4)

#define HP_SZ ((size_t)NROWS*DD)

// ---------------- device scratch ----------------
__device__ __half  g_xfH[NROWS*DD];      // xf fp16 row-major
__device__ __half2 g_xfP[(NROWS/2)*DD];  // xf k-pair-packed [k/2][n]
__device__ __half  g_hp[4*NROWS*DD];     // partials: [mat(2)][kh(2)] half-K results
__device__ __half  g_yx[NROWS*DD];       // xf @ W^T, fp16
__device__ __half2 g_WP  [(DD/2)*DD];
__device__ __half2 g_WudP[(DD/2)*DD];
__device__ __half2 g_WlrP[(DD/2)*DD];
__device__ __half2 g_WgP [(DD/2)*DD];
__device__ float   g_pooled[DD];
__device__ float   g_nsum;

// ---------------- helpers ----------------
__device__ __forceinline__ uint32_t smem_u32(const void* p){
    return (uint32_t)__cvta_generic_to_shared(p);
}
__device__ __forceinline__ void cpasync16(uint32_t s, const void* g){
    asm volatile("cp.async.cg.shared.global [%0], [%1], 16;\n" :: "r"(s), "l"(g));
}
__device__ __forceinline__ void hmma(float* c, const uint32_t a[4], const uint32_t b[2]){
    asm volatile(
      "mma.sync.aligned.m16n8k16.row.col.f32.f16.f16.f32 "
      "{%0,%1,%2,%3},{%4,%5,%6,%7},{%8,%9},{%0,%1,%2,%3};\n"
      : "+f"(c[0]),"+f"(c[1]),"+f"(c[2]),"+f"(c[3])
      : "r"(a[0]),"r"(a[1]),"r"(a[2]),"r"(a[3]),"r"(b[0]),"r"(b[1]));
}
__device__ __forceinline__ void ldsm4(uint32_t* r, uint32_t addr){
    asm volatile("ldmatrix.sync.aligned.m8n8.x4.shared.b16 {%0,%1,%2,%3}, [%4];"
        : "=r"(r[0]),"=r"(r[1]),"=r"(r[2]),"=r"(r[3]) : "r"(addr));
}
__device__ __forceinline__ uint32_t lds32(uint32_t addr){
    uint32_t v; asm volatile("ld.shared.b32 %0, [%1];" : "=r"(v) : "r"(addr)); return v;
}
__device__ __forceinline__ void sts_u2(uint32_t addr, uint32_t x, uint32_t y){
    asm volatile("st.shared.v2.b32 [%0], {%1,%2};" :: "r"(addr), "r"(x), "r"(y));
}
__device__ __forceinline__ void sts_u4(uint32_t addr, uint4 v){
    asm volatile("st.shared.v4.b32 [%0], {%1,%2,%3,%4};"
        :: "r"(addr), "r"(v.x), "r"(v.y), "r"(v.z), "r"(v.w));
}
__device__ __forceinline__ uint32_t hadd2u(uint32_t a, uint32_t b){
    __half2 r = __hadd2(*(__half2*)&a, *(__half2*)&b); return *(uint32_t*)&r;
}
// conflict-free A-chunk mapping for 16B STS at ASTRIDE=80
__device__ __forceinline__ void amap(int idx, int& m, int& c){
    int q = idx>>2; c = idx&3;
    m = (q & 0x78) | ((q & 1) << 2) | ((q >> 1) & 3);
}

#define ZERO_ACC(acc) do{ _Pragma("unroll") for(int i_=0;i_<4;i_++) \
    _Pragma("unroll") for(int j_=0;j_<4;j_++) \
    _Pragma("unroll") for(int q_=0;q_<4;q_++) acc[i_][j_][q_]=0.f; }while(0)

// One BK=32 tile of MMAs. A via ldmatrix.x4, B via LDS.32.
__device__ __forceinline__ void compute_tile(uint32_t As, uint32_t Bs,
                                             float (&acc)[4][4][4],
                                             int wm,int wn,int gq,int tq,int lane){
    const uint32_t arow = lane & 15;
    const uint32_t acol = (lane >> 4) * 16;
    const uint32_t abase = As + (wm + arow)*ASTRIDE + acol;
    const uint32_t bbase = Bs + tq*BSTRIDE + (wn + gq)*4;
    #pragma unroll
    for(int kk=0;kk<2;kk++){
        uint32_t a[4][4], b[4][2];
        #pragma unroll
        for(int mt=0;mt<4;mt++)
            ldsm4(a[mt], abase + mt*16*ASTRIDE + kk*32);
        #pragma unroll
        for(int nt=0;nt<4;nt++){
            uint32_t p = bbase + kk*8*BSTRIDE + nt*32;
            b[nt][0] = lds32(p);
            b[nt][1] = lds32(p + 4*BSTRIDE);
        }
        #pragma unroll
        for(int mt=0;mt<4;mt++)
            #pragma unroll
            for(int nt=0;nt<4;nt++)
                hmma(acc[mt][nt], a[mt], b[nt]);
    }
}

// ---- mainloop A: A fp32 global, converted in-flight ----
template<class FA, class FB>
__device__ __forceinline__ void mainloop_conv(int nk, float (&acc)[4][4][4],
                                              char* sm, FA getAf4, FB getB16){
    const int tid = threadIdx.x;
    const uint32_t smb = smem_u32(sm);
    const int lane=tid&31, warp=tid>>5;
    const int wm=(warp>>2)*64, wn=(warp&3)*32, gq=lane>>2, tq=lane&3;

    float4 av[4];
    #pragma unroll
    for(int r=0;r<4;r++) av[r] = __ldg(getAf4(0, tid + r*256));

    #pragma unroll
    for(int pg=0; pg<2; pg++){
        if(pg < nk){
            const uint32_t bb = smb + pg*STAGE + A_TILE;
            #pragma unroll
            for(int r=0;r<2;r++){
                int idx = tid + r*256; int p=idx>>5, c=idx&31;
                cpasync16(bb + p*BSTRIDE + c*16, getB16(pg, idx));
            }
        }
        asm volatile("cp.async.commit_group;" ::: "memory");
    }

    for(int kt=0; kt<nk; ++kt){
        const uint32_t ab = smb + (kt&3)*STAGE;
        #pragma unroll
        for(int r=0;r<4;r++){
            int idx = tid + r*256; int m=idx>>3, c=idx&7;
            __half2 h0 = __floats2half2_rn(av[r].x, av[r].y);
            __half2 h1 = __floats2half2_rn(av[r].z, av[r].w);
            sts_u2(ab + m*ASTRIDE + c*8, *(uint32_t*)&h0, *(uint32_t*)&h1);
        }
        if(kt+1 < nk){
            #pragma unroll
            for(int r=0;r<4;r++) av[r] = __ldg(getAf4(kt+1, tid + r*256));
        }
        if(kt+2 < nk){
            const uint32_t bb = smb + ((kt+2)&3)*STAGE + A_TILE;
            #pragma unroll
            for(int r=0;r<2;r++){
                int idx = tid + r*256; int p=idx>>5, c=idx&31;
                cpasync16(bb + p*BSTRIDE + c*16, getB16(kt+2, idx));
            }
        }
        asm volatile("cp.async.commit_group;" ::: "memory");
        asm volatile("cp.async.wait_group 2;" ::: "memory");
        __syncthreads();
        compute_tile(ab, ab + A_TILE, acc, wm, wn, gq, tq, lane);
    }
}

// ---- mainloop B: both operands via cp.async ----
template<class FA, class FB>
__device__ __forceinline__ void mainloop_cp(int nk, float (&acc)[4][4][4],
                                            char* sm, FA getA16, FB getB16){
    const int tid = threadIdx.x;
    const uint32_t smb = smem_u32(sm);
    const int lane=tid&31, warp=tid>>5;
    const int wm=(warp>>2)*64, wn=(warp&3)*32, gq=lane>>2, tq=lane&3;

    auto stage_loads = [&](int s){
        const uint32_t ab = smb + (s&3)*STAGE;
        const uint32_t bb = ab + A_TILE;
        #pragma unroll
        for(int r=0;r<2;r++){
            int idx = tid + r*256; int m=idx>>2, c=idx&3;
            cpasync16(ab + m*ASTRIDE + c*16, getA16(s, idx));
        }
        #pragma unroll
        for(int r=0;r<2;r++){
            int idx = tid + r*256; int p=idx>>5, c=idx&31;
            cpasync16(bb + p*BSTRIDE + c*16, getB16(s, idx));
        }
    };

    #pragma unroll
    for(int pg=0; pg<2; pg++){
        if(pg < nk) stage_loads(pg);
        asm volatile("cp.async.commit_group;" ::: "memory");
    }
    for(int kt=0; kt<nk; ++kt){
        if(kt+2 < nk) stage_loads(kt+2);
        asm volatile("cp.async.commit_group;" ::: "memory");
        asm volatile("cp.async.wait_group 2;" ::: "memory");
        __syncthreads();
        const uint32_t ab = smb + (kt&3)*STAGE;
        compute_tile(ab, ab + A_TILE, acc, wm, wn, gq, tq, lane);
    }
}

// ---- mainloop C: A = sum of two fp16 sources (LDG + HADD2 + STS), B via cp.async ----
template<class FA0, class FA1, class FB>
__device__ __forceinline__ void mainloop_sum(int nk, float (&acc)[4][4][4],
                                             char* sm, FA0 getA0, FA1 getA1, FB getB16){
    const int tid = threadIdx.x;
    const uint32_t smb = smem_u32(sm);
    const int lane=tid&31, warp=tid>>5;
    const int wm=(warp>>2)*64, wn=(warp&3)*32, gq=lane>>2, tq=lane&3;
    int am[2], ac[2];
    amap(tid,     am[0], ac[0]);
    amap(tid+256, am[1], ac[1]);

    auto cpB = [&](int s){
        const uint32_t bb = smb + (s&3)*STAGE + A_TILE;
        #pragma unroll
        for(int r=0;r<2;r++){
            int idx = tid + r*256; int p=idx>>5, c=idx&31;
            cpasync16(bb + p*BSTRIDE + c*16, getB16(s, idx));
        }
    };
    auto ldA = [&](int s, uint4 (*sv)[2]){
        #pragma unroll
        for(int r=0;r<2;r++){
            sv[r][0] = __ldg((const uint4*)getA0(s, am[r], ac[r]));
            sv[r][1] = __ldg((const uint4*)getA1(s, am[r], ac[r]));
        }
    };
    auto stA = [&](int s, uint4 (*sv)[2]){
        const uint32_t ab = smb + (s&3)*STAGE;
        #pragma unroll
        for(int r=0;r<2;r++){
            uint4 v;
            v.x = hadd2u(sv[r][0].x, sv[r][1].x);
            v.y = hadd2u(sv[r][0].y, sv[r][1].y);
            v.z = hadd2u(sv[r][0].z, sv[r][1].z);
            v.w = hadd2u(sv[r][0].w, sv[r][1].w);
            sts_u4(ab + am[r]*ASTRIDE + ac[r]*16, v);
        }
    };

    uint4 sv[2][2];
    ldA(0, sv);
    cpB(0); asm volatile("cp.async.commit_group;" ::: "memory");
    if(nk>1) cpB(1);
    asm volatile("cp.async.commit_group;" ::: "memory");

    for(int kt=0; kt<nk; ++kt){
        stA(kt, sv);
        if(kt+1 < nk) ldA(kt+1, sv);
        if(kt+2 < nk) cpB(kt+2);
        asm volatile("cp.async.commit_group;" ::: "memory");
        asm volatile("cp.async.wait_group 2;" ::: "memory");
        __syncthreads();
        const uint32_t ab = smb + (kt&3)*STAGE;
        compute_tile(ab, ab + A_TILE, acc, wm, wn, gq, tq, lane);
    }
}

// ---------------- prep ----------------
__global__ void prep_kernel(const float* __restrict__ xf, const float* __restrict__ mask,
                            const float* __restrict__ W,  const float* __restrict__ Wud,
                            const float* __restrict__ Wlr,const float* __restrict__ Wg){
    const int bx = blockIdx.x, tid = threadIdx.x;
    if(bx < 2048){
        int idx = bx*256 + tid;
        int p = idx >> 7, n4 = (idx & 127)*4;
        float4 v0 = *(const float4*)(xf + (size_t)(2*p)*DD + n4);
        float4 v1 = *(const float4*)(xf + (size_t)(2*p+1)*DD + n4);
        __half2 r0 = __floats2half2_rn(v0.x, v0.y), r1 = __floats2half2_rn(v0.z, v0.w);
        __half2 r2 = __floats2half2_rn(v1.x, v1.y), r3 = __floats2half2_rn(v1.z, v1.w);
        uint2 u0; u0.x=*(uint32_t*)&r0; u0.y=*(uint32_t*)&r1;
        uint2 u1; u1.x=*(uint32_t*)&r2; u1.y=*(uint32_t*)&r3;
        *(uint2*)(g_xfH + (size_t)(2*p)*DD + n4)   = u0;
        *(uint2*)(g_xfH + (size_t)(2*p+1)*DD + n4) = u1;
        __half2 p0 = __floats2half2_rn(v0.x, v1.x);
        __half2 p1 = __floats2half2_rn(v0.y, v1.y);
        __half2 p2 = __floats2half2_rn(v0.z, v1.z);
        __half2 p3 = __floats2half2_rn(v0.w, v1.w);
        uint4 up; up.x=*(uint32_t*)&p0; up.y=*(uint32_t*)&p1; up.z=*(uint32_t*)&p2; up.w=*(uint32_t*)&p3;
        *(uint4*)(g_xfP + (size_t)p*DD + n4) = up;
    } else if(bx < 4096){
        int i = bx - 2048;
        const float* src; __half2* dst;
        switch(i >> 9){
            case 0: src=W;   dst=g_WP;   break;
            case 1: src=Wud; dst=g_WudP; break;
            case 2: src=Wlr; dst=g_WlrP; break;
            default:src=Wg;  dst=g_WgP;  break;
        }
        int idx = (i & 511)*256 + tid;
        int p = idx >> 9, n = idx & 511;
        float2 v = *(const float2*)(src + (size_t)n*DD + 2*p);
        dst[(size_t)p*DD + n] = __floats2half2_rn(v.x, v.y);
    } else {
        __shared__ float red[256];
        float s=0.f;
        for(int i=tid;i<NROWS;i+=256) s += mask[i];
        red[tid]=s; __syncthreads();
        for(int st=128;st>0;st>>=1){
            if(tid<st) red[tid]+=red[tid+st];
            __syncthreads();
        }
        if(tid==0) g_nsum = red[0];
        g_pooled[tid]     = 0.f;
        g_pooled[tid+256] = 0.f;
    }
}

// ---------------- mega: half-K big aggregations + pool + y_x ----------------
// Big CTA map: col fastest (R9 win) so the 4 CTAs sharing an A row-slab co-reside.
__global__ void __launch_bounds__(256,2) mega_kernel(
        const float* __restrict__ a_ud, const float* __restrict__ a_lr,
        const float* __restrict__ b_g,  const float* __restrict__ mask){
    extern __shared__ char sm[];
    const int bx = blockIdx.x;
    const int lane=threadIdx.x&31, warp=threadIdx.x>>5;
    const int wm=(warp>>2)*64, wn=(warp&3)*32, gq=lane>>2, tq=lane&3;
    float acc[4][4][4]; ZERO_ACC(acc);

    if(bx < 1024){
        // mat(2) x half(2) x row(64) x col(4), col fastest
        const int mat = bx>>9, half = (bx>>8)&1, row = (bx>>2)&63, col = bx&3;
        const float* A = mat ? a_lr : a_ud;
        __half* C = g_hp + (size_t)(mat*2 + half)*HP_SZ;
        const size_t rowBase = (size_t)row * BM;
        const int colBase = col * BN;
        const int kOff = half * 4096;
        auto getAf4=[&](int s,int idx){
            int m=idx>>3, c=idx&7;
            return (const float4*)(A + (rowBase+m)*NROWS + kOff + s*BK + c*4);
        };
        auto getB16=[&](int s,int idx){
            int p=idx>>5, c=idx&31;
            return (const void*)(g_xfP + (size_t)(kOff/2 + s*16 + p)*DD + colBase + c*4);
        };
        mainloop_conv(4096/BK, acc, sm, getAf4, getB16);
        #pragma unroll
        for(int mt=0;mt<4;mt++){
            size_t r0 = rowBase + wm + mt*16 + gq;
            #pragma unroll
            for(int nt=0;nt<4;nt++){
                int c0 = colBase + wn + nt*8 + 2*tq;
                *(__half2*)(C + r0*DD + c0)     = __floats2half2_rn(acc[mt][nt][0], acc[mt][nt][1]);
                *(__half2*)(C + (r0+8)*DD + c0) = __floats2half2_rn(acc[mt][nt][2], acc[mt][nt][3]);
            }
        }
    } else if(bx < 1280){
        const int i = bx - 1024;
        const size_t rowBase = (size_t)(i & 63) * BM;
        const int colBase = (i >> 6) * BN;
        auto getA16=[&](int s,int idx){
            int m=idx>>2, c=idx&3;
            return (const void*)(g_xfH + (rowBase+m)*DD + s*BK + c*8);
        };
        auto getB16=[&](int s,int idx){
            int p=idx>>5, c=idx&31;
            return (const void*)(g_WgP + (size_t)(s*16+p)*DD + colBase + c*4);
        };
        mainloop_cp(DD/BK, acc, sm, getA16, getB16);
        float cs[4][2];
        #pragma unroll
        for(int nt=0;nt<4;nt++){ cs[nt][0]=0.f; cs[nt][1]=0.f; }
        #pragma unroll
        for(int mt=0;mt<4;mt++){
            size_t r0 = rowBase + wm + mt*16 + gq;
            float m0 = mask[r0], m8 = mask[r0+8];
            #pragma unroll
            for(int nt=0;nt<4;nt++){
                int c0 = colBase + wn + nt*8 + 2*tq;
                float bg0 = b_g[c0], bg1 = b_g[c0+1];
                cs[nt][0] += fmaxf(acc[mt][nt][0]+bg0,0.f)*m0 + fmaxf(acc[mt][nt][2]+bg0,0.f)*m8;
                cs[nt][1] += fmaxf(acc[mt][nt][1]+bg1,0.f)*m0 + fmaxf(acc[mt][nt][3]+bg1,0.f)*m8;
            }
        }
        #pragma unroll
        for(int nt=0;nt<4;nt++){
            #pragma unroll
            for(int j=0;j<2;j++){
                float v = cs[nt][j];
                v += __shfl_xor_sync(0xffffffffu, v, 4);
                v += __shfl_xor_sync(0xffffffffu, v, 8);
                v += __shfl_xor_sync(0xffffffffu, v, 16);
                if(lane < 4)
                    atomicAdd(&g_pooled[colBase + wn + nt*8 + 2*tq + j], v);
            }
        }
    } else {
        const int i = bx - 1280;
        const size_t rowBase = (size_t)(i & 63) * BM;
        const int colBase = (i >> 6) * BN;
        auto getA16=[&](int s,int idx){
            int m=idx>>2, c=idx&3;
            return (const void*)(g_xfH + (rowBase+m)*DD + s*BK + c*8);
        };
        auto getB16=[&](int s,int idx){
            int p=idx>>5, c=idx&31;
            return (const void*)(g_WP + (size_t)(s*16+p)*DD + colBase + c*4);
        };
        mainloop_cp(DD/BK, acc, sm, getA16, getB16);
        #pragma unroll
        for(int mt=0;mt<4;mt++){
            size_t r0 = rowBase + wm + mt*16 + gq;
            #pragma unroll
            for(int nt=0;nt<4;nt++){
                int c0 = colBase + wn + nt*8 + 2*tq;
                *(__half2*)(g_yx + r0*DD + c0)     = __floats2half2_rn(acc[mt][nt][0], acc[mt][nt][1]);
                *(__half2*)(g_yx + (r0+8)*DD + c0) = __floats2half2_rn(acc[mt][nt][2], acc[mt][nt][3]);
            }
        }
    }
}

// ---------------- final: h = relu( y_x + h_ud@Wud^T + h_lr@Wlr^T + bias ) ----------------
__global__ void __launch_bounds__(256,2) final_kernel(
        const float* __restrict__ W_go,
        const float* __restrict__ b,   const float* __restrict__ b_ud,
        const float* __restrict__ b_lr,const float* __restrict__ b_go,
        float* __restrict__ out){
    extern __shared__ char sm[];
    float* hg    = (float*)(sm + HG_OFF);
    float* sbias = (float*)(sm + SB_OFF);
    const int tid = threadIdx.x;
    const size_t rowBase = (size_t)(blockIdx.x & 63) * BM;
    const int colBase = (blockIdx.x >> 6) * BN;

    {
        float inv = 1.0f / g_nsum;
        hg[tid]     = g_pooled[tid]*inv;
        hg[tid+256] = g_pooled[tid+256]*inv;
    }
    __syncthreads();
    if(blockIdx.x == 0){
        out[HP_SZ + tid]       = hg[tid];
        out[HP_SZ + tid + 256] = hg[tid+256];
    }
    {
        int j = colBase + (tid>>1);
        int k0 = (tid&1)*256;
        const float4* wr = (const float4*)(W_go + (size_t)j*DD + k0);
        float s = 0.f;
        #pragma unroll 8
        for(int q=0;q<64;q++){
            float4 wv = wr[q];
            s += hg[k0+4*q]*wv.x + hg[k0+4*q+1]*wv.y + hg[k0+4*q+2]*wv.z + hg[k0+4*q+3]*wv.w;
        }
        s += __shfl_xor_sync(0xffffffffu, s, 1);
        if((tid&1)==0) sbias[tid>>1] = s + b[j] + b_ud[j] + b_lr[j] + b_go[j];
    }
    __syncthreads();

    float acc[4][4][4]; ZERO_ACC(acc);
    // K=1024: seg 0 = h_ud (partials 0,1), seg 1 = h_lr (partials 2,3)
    auto getA0=[&](int s,int m,int c){
        int seg = s>>4;
        const __half* A = g_hp + (size_t)(seg*2)*HP_SZ;
        return (const void*)(A + (rowBase+m)*DD + (s&15)*BK + c*8);
    };
    auto getA1=[&](int s,int m,int c){
        int seg = s>>4;
        const __half* A = g_hp + (size_t)(seg*2+1)*HP_SZ;
        return (const void*)(A + (rowBase+m)*DD + (s&15)*BK + c*8);
    };
    auto getB16=[&](int s,int idx){
        int p=idx>>5, c=idx&31; int seg=s>>4;
        const __half2* B = seg ? g_WlrP : g_WudP;
        return (const void*)(B + (size_t)((s&15)*16+p)*DD + colBase + c*4);
    };
    mainloop_sum(2*DD/BK, acc, sm, getA0, getA1, getB16);

    const int lane=tid&31, warp=tid>>5;
    const int wm=(warp>>2)*64, wn=(warp&3)*32, gq=lane>>2, tq=lane&3;
    #pragma unroll
    for(int mt=0;mt<4;mt++){
        size_t r0 = rowBase + wm + mt*16 + gq;
        #pragma unroll
        for(int nt=0;nt<4;nt++){
            int c0 = colBase + wn + nt*8 + 2*tq;
            float bb0 = sbias[c0-colBase], bb1 = sbias[c0-colBase+1];
            float2 y0 = __half22float2(*(const __half2*)(g_yx + r0*DD + c0));
            float2 y2 = __half22float2(*(const __half2*)(g_yx + (r0+8)*DD + c0));
            float2 v0 = make_float2(fmaxf(acc[mt][nt][0]+y0.x+bb0,0.f),
                                    fmaxf(acc[mt][nt][1]+y0.y+bb1,0.f));
            float2 v2 = make_float2(fmaxf(acc[mt][nt][2]+y2.x+bb0,0.f),
                                    fmaxf(acc[mt][nt][3]+y2.y+bb1,0.f));
            *(float2*)(out + r0*DD + c0)     = v0;
            *(float2*)(out + (r0+8)*DD + c0) = v2;
        }
    }
}

// ---------------- launch ----------------
extern "C" void kernel_launch(void* const* d_in, const int* in_sizes, int n_in,
                              void* d_out, int out_size){
    const float* x    = (const float*)d_in[0];
    const float* mask = (const float*)d_in[1];
    const float* a_ud = (const float*)d_in[2];
    const float* a_lr = (const float*)d_in[3];
    const float* W    = (const float*)d_in[4];
    const float* b    = (const float*)d_in[5];
    const float* W_ud = (const float*)d_in[6];
    const float* b_ud = (const float*)d_in[7];
    const float* W_lr = (const float*)d_in[8];
    const float* b_lr = (const float*)d_in[9];
    const float* W_g  = (const float*)d_in[10];
    const float* b_g  = (const float*)d_in[11];
    const float* W_go = (const float*)d_in[12];
    const float* b_go = (const float*)d_in[13];
    float* out = (float*)d_out;

    cudaFuncSetAttribute(mega_kernel,  cudaFuncAttributeMaxDynamicSharedMemorySize, SMEM_TOTAL);
    cudaFuncSetAttribute(final_kernel, cudaFuncAttributeMaxDynamicSharedMemorySize, FINAL_SMEM);

    prep_kernel<<<4097, 256>>>(x, mask, W, W_ud, W_lr, W_g);
    mega_kernel<<<1536, 256, SMEM_TOTAL>>>(a_ud, a_lr, b_g, mask);
    final_kernel<<<256, 256, FINAL_SMEM>>>(W_go, b, b_ud, b_lr, b_go, out);
}